// round 2
// baseline (speedup 1.0000x reference)
#include <cuda_runtime.h>
#include <math.h>

#define NH   16
#define NKV  8
#define D    128
#define HID  2048
#define QKV_N ((NH + 2 * NKV) * D)   /* 4096 */
#define MAXT 2048

/* ---------------- scratch (no allocations allowed) ---------------- */
__device__ float g_qkv[(size_t)MAXT * QKV_N];       /* 32 MB */
__device__ float g_q  [(size_t)MAXT * NH  * D];     /* 16 MB */
__device__ float g_k  [(size_t)MAXT * NKV * D];     /*  8 MB */
__device__ float g_attn[(size_t)MAXT * NH * D];     /* 16 MB */

/* ---------------- tiled fp32 GEMM: C[M,N] = A[M,K] @ B[K,N] -------- */
#define BM 64
#define BN 64
#define BK 16

__device__ __forceinline__ void sgemm_body(const float* __restrict__ A,
                                           const float* __restrict__ B,
                                           float* __restrict__ C,
                                           int M, int N, int K)
{
    __shared__ __align__(16) float As[BK][BM + 4];
    __shared__ __align__(16) float Bs[BK][BN + 4];

    const int tid = threadIdx.x;
    const int tx  = tid & 15;
    const int ty  = tid >> 4;
    const int m0  = blockIdx.y * BM;
    const int n0  = blockIdx.x * BN;

    float acc[4][4];
#pragma unroll
    for (int i = 0; i < 4; i++)
#pragma unroll
        for (int j = 0; j < 4; j++) acc[i][j] = 0.f;

    const int ar = tid >> 2;          /* 0..63 */
    const int ac = (tid & 3) << 2;    /* 0,4,8,12 */
    const int br = tid >> 4;          /* 0..15 */
    const int bc = (tid & 15) << 2;   /* 0..60 */

    for (int k0 = 0; k0 < K; k0 += BK) {
        float4 a4 = *(const float4*)&A[(size_t)(m0 + ar) * K + k0 + ac];
        As[ac + 0][ar] = a4.x;
        As[ac + 1][ar] = a4.y;
        As[ac + 2][ar] = a4.z;
        As[ac + 3][ar] = a4.w;
        *(float4*)&Bs[br][bc] = *(const float4*)&B[(size_t)(k0 + br) * N + n0 + bc];
        __syncthreads();

#pragma unroll
        for (int k = 0; k < BK; k++) {
            float4 av = *(const float4*)&As[k][ty * 4];
            float4 bv = *(const float4*)&Bs[k][tx * 4];
            acc[0][0] += av.x * bv.x; acc[0][1] += av.x * bv.y;
            acc[0][2] += av.x * bv.z; acc[0][3] += av.x * bv.w;
            acc[1][0] += av.y * bv.x; acc[1][1] += av.y * bv.y;
            acc[1][2] += av.y * bv.z; acc[1][3] += av.y * bv.w;
            acc[2][0] += av.z * bv.x; acc[2][1] += av.z * bv.y;
            acc[2][2] += av.z * bv.z; acc[2][3] += av.z * bv.w;
            acc[3][0] += av.w * bv.x; acc[3][1] += av.w * bv.y;
            acc[3][2] += av.w * bv.z; acc[3][3] += av.w * bv.w;
        }
        __syncthreads();
    }

#pragma unroll
    for (int i = 0; i < 4; i++) {
        float4 r = make_float4(acc[i][0], acc[i][1], acc[i][2], acc[i][3]);
        *(float4*)&C[(size_t)(m0 + ty * 4 + i) * N + n0 + tx * 4] = r;
    }
}

__global__ __launch_bounds__(256) void qkv_gemm(const float* __restrict__ A,
                                                const float* __restrict__ B,
                                                int T)
{
    sgemm_body(A, B, g_qkv, T, QKV_N, HID);
}

__global__ __launch_bounds__(256) void out_gemm(const float* __restrict__ B,
                                                float* __restrict__ C,
                                                int T)
{
    sgemm_body(g_attn, B, C, T, HID, HID);
}

/* ---------------- RMSNorm + RoPE for q and k ----------------------- */
__global__ __launch_bounds__(128) void normrope_kernel(const int* __restrict__ positions,
                                                       const float* __restrict__ q_norm_w,
                                                       const float* __restrict__ k_norm_w,
                                                       int T)
{
    const int t = blockIdx.x;
    const int h = blockIdx.y;            /* 0..NH-1 => q head, else kv head */
    const int d = threadIdx.x;           /* 0..127 */

    const float* src;
    const float* w;
    float* dst;
    if (h < NH) {
        src = g_qkv + (size_t)t * QKV_N + h * D;
        w   = q_norm_w;
        dst = g_q + ((size_t)t * NH + h) * D;
    } else {
        int hk = h - NH;
        src = g_qkv + (size_t)t * QKV_N + NH * D + hk * D;
        w   = k_norm_w;
        dst = g_k + ((size_t)t * NKV + hk) * D;
    }

    float x = src[d];
    float ss = x * x;
#pragma unroll
    for (int o = 16; o > 0; o >>= 1) ss += __shfl_xor_sync(0xFFFFFFFFu, ss, o);

    __shared__ float red[4];
    __shared__ float s[D];
    if ((d & 31) == 0) red[d >> 5] = ss;
    __syncthreads();
    float var = (red[0] + red[1] + red[2] + red[3]) * (1.0f / (float)D);
    float nx = x * rsqrtf(var + 1e-6f) * w[d];
    s[d] = nx;
    __syncthreads();

    if (d < D / 2) {
        float p = (float)positions[t];
        float inv = (float)(1.0 / pow(1000000.0, (double)d / (double)(D / 2)));
        float ang = p * inv;
        float c = cosf(ang);
        float si = sinf(ang);
        float x1 = s[d];
        float x2 = s[d + D / 2];
        dst[d]         = x1 * c - x2 * si;
        dst[d + D / 2] = x2 * c + x1 * si;
    }
}

/* ---------------- causal flash attention (fp32) --------------------- */
#define AT_BM 128
#define AT_BN 32
#define QS_LD 132   /* row stride (floats): conflict-free LDS.128 phases */

extern __shared__ float s_attn[];

__global__ __launch_bounds__(128) void attn_kernel(int T)
{
    float* qs = s_attn;                       /* 128 x 132 */
    float* ks = qs + AT_BM * QS_LD;           /*  32 x 132 */
    float* vs = ks + AT_BN * QS_LD;           /*  32 x 132 */

    const int h   = blockIdx.y;
    const int hk  = h >> 1;                   /* group = NH/NKV = 2 */
    const int m0  = blockIdx.x * AT_BM;
    const int tid = threadIdx.x;
    const float scale = 0.08838834764831845f; /* 1/sqrt(128) */

    /* load + pre-scale q tile (coalesced: 32 float4 lanes per row) */
    {
        const int c = tid & 31;
        const int r = tid >> 5;
#pragma unroll
        for (int p = 0; p < AT_BM / 4; p++) {
            int row = r + p * 4;
            float4 v = *(const float4*)&g_q[((size_t)(m0 + row) * NH + h) * D + c * 4];
            v.x *= scale; v.y *= scale; v.z *= scale; v.w *= scale;
            *(float4*)&qs[row * QS_LD + c * 4] = v;
        }
    }

    float4 acc[32];
#pragma unroll
    for (int u = 0; u < 32; u++) acc[u] = make_float4(0.f, 0.f, 0.f, 0.f);
    float mrow = -1e30f;
    float lrow = 0.f;
    const int qi = m0 + tid;

    const int ntiles = (m0 + AT_BM) / AT_BN;
    for (int kt = 0; kt < ntiles; kt++) {
        const int k0 = kt * AT_BN;
        __syncthreads();   /* previous tile's smem fully consumed */
        {
            const int c = tid & 31;
            const int r = tid >> 5;
#pragma unroll
            for (int p = 0; p < AT_BN / 4; p++) {
                int row = r + p * 4;
                *(float4*)&ks[row * QS_LD + c * 4] =
                    *(const float4*)&g_k[((size_t)(k0 + row) * NKV + hk) * D + c * 4];
                *(float4*)&vs[row * QS_LD + c * 4] =
                    *(const float4*)&g_qkv[(size_t)(k0 + row) * QKV_N + (NH + NKV) * D + hk * D + c * 4];
            }
        }
        __syncthreads();

        /* scores: s[jj] = q_row . k_jj  (q in regs per 32-dim chunk, k broadcast) */
        float s[AT_BN];
#pragma unroll
        for (int jj = 0; jj < AT_BN; jj++) s[jj] = 0.f;
#pragma unroll
        for (int d0 = 0; d0 < D; d0 += 32) {
            float q[32];
#pragma unroll
            for (int u = 0; u < 8; u++) {
                float4 t4 = *(const float4*)&qs[tid * QS_LD + d0 + u * 4];
                q[u * 4 + 0] = t4.x; q[u * 4 + 1] = t4.y;
                q[u * 4 + 2] = t4.z; q[u * 4 + 3] = t4.w;
            }
            for (int jj = 0; jj < AT_BN; jj++) {
                float sj = 0.f;
#pragma unroll
                for (int u = 0; u < 8; u++) {
                    float4 k4 = *(const float4*)&ks[jj * QS_LD + d0 + u * 4];
                    sj += q[u * 4 + 0] * k4.x + q[u * 4 + 1] * k4.y
                        + q[u * 4 + 2] * k4.z + q[u * 4 + 3] * k4.w;
                }
                s[jj] += sj;
            }
        }

        /* causal mask + online softmax */
        float mt = mrow;
#pragma unroll
        for (int jj = 0; jj < AT_BN; jj++) {
            if (k0 + jj > qi) s[jj] = -1e30f;
            mt = fmaxf(mt, s[jj]);
        }
        float corr = __expf(mrow - mt);
        mrow = mt;
        float psum = 0.f;
#pragma unroll
        for (int jj = 0; jj < AT_BN; jj++) {
            float pj = __expf(s[jj] - mt);
            s[jj] = pj;
            psum += pj;
        }
        lrow = lrow * corr + psum;

#pragma unroll
        for (int u = 0; u < 32; u++) {
            acc[u].x *= corr; acc[u].y *= corr;
            acc[u].z *= corr; acc[u].w *= corr;
        }
        for (int jj = 0; jj < AT_BN; jj++) {
            float pj = s[jj];
#pragma unroll
            for (int u = 0; u < 32; u++) {
                float4 v4 = *(const float4*)&vs[jj * QS_LD + u * 4];
                acc[u].x += pj * v4.x; acc[u].y += pj * v4.y;
                acc[u].z += pj * v4.z; acc[u].w += pj * v4.w;
            }
        }
    }

    const float inv = 1.f / lrow;
#pragma unroll
    for (int u = 0; u < 32; u++) {
        float4 r = acc[u];
        r.x *= inv; r.y *= inv; r.z *= inv; r.w *= inv;
        *(float4*)&g_attn[(size_t)qi * (NH * D) + h * D + u * 4] = r;
    }
}

/* ---------------- launch -------------------------------------------- */
extern "C" void kernel_launch(void* const* d_in, const int* in_sizes, int n_in,
                              void* d_out, int out_size)
{
    const int*   positions = (const int*)d_in[0];
    const float* hidden    = (const float*)d_in[1];
    const float* w_qkv     = (const float*)d_in[2];
    const float* q_norm_w  = (const float*)d_in[3];
    const float* k_norm_w  = (const float*)d_in[4];
    const float* w_o       = (const float*)d_in[5];
    float*       out       = (float*)d_out;
    const int    T         = in_sizes[0];   /* 2048 */

    /* 1) QKV projection: [T,HID] @ [HID,4096] */
    dim3 g1(QKV_N / BN, T / BM);
    qkv_gemm<<<g1, 256>>>(hidden, w_qkv, T);

    /* 2) RMSNorm + RoPE for q and k */
    dim3 g2(T, NH + NKV);
    normrope_kernel<<<g2, 128>>>(positions, q_norm_w, k_norm_w, T);

    /* 3) causal GQA flash attention */
    int smem = (AT_BM + 2 * AT_BN) * QS_LD * (int)sizeof(float);
    cudaFuncSetAttribute(attn_kernel, cudaFuncAttributeMaxDynamicSharedMemorySize, smem);
    dim3 g3(T / AT_BM, NH);
    attn_kernel<<<g3, 128, smem>>>(T);

    /* 4) output projection: [T,2048] @ [2048,2048] */
    dim3 g4(HID / BN, T / BM);
    out_gemm<<<g4, 256>>>(w_o, out, T);
}

// round 3
// speedup vs baseline: 1.1126x; 1.1126x over previous
#include <cuda_runtime.h>
#include <math.h>

#define NH   16
#define NKV  8
#define D    128
#define HID  2048
#define QKV_N ((NH + 2 * NKV) * D)   /* 4096 */
#define MAXT 2048

/* ---------------- scratch (no allocations allowed) ---------------- */
__device__ float g_qkv[(size_t)MAXT * QKV_N];       /* 32 MB */
__device__ float g_q  [(size_t)MAXT * NH  * D];     /* 16 MB */
__device__ float g_k  [(size_t)MAXT * NKV * D];     /*  8 MB */
__device__ float g_attn[(size_t)MAXT * NH * D];     /* 16 MB */

/* ---------------- tiled fp32 GEMM: C[M,N] = A[M,K] @ B[K,N] -------- */
#define BM 64
#define BN 64
#define BK 16

__device__ __forceinline__ void sgemm_body(const float* __restrict__ A,
                                           const float* __restrict__ B,
                                           float* __restrict__ C,
                                           int M, int N, int K)
{
    __shared__ __align__(16) float As[BK][BM + 4];
    __shared__ __align__(16) float Bs[BK][BN + 4];

    const int tid = threadIdx.x;
    const int tx  = tid & 15;
    const int ty  = tid >> 4;
    const int m0  = blockIdx.y * BM;
    const int n0  = blockIdx.x * BN;

    float acc[4][4];
#pragma unroll
    for (int i = 0; i < 4; i++)
#pragma unroll
        for (int j = 0; j < 4; j++) acc[i][j] = 0.f;

    const int ar = tid >> 2;          /* 0..63 */
    const int ac = (tid & 3) << 2;    /* 0,4,8,12 */
    const int br = tid >> 4;          /* 0..15 */
    const int bc = (tid & 15) << 2;   /* 0..60 */

    for (int k0 = 0; k0 < K; k0 += BK) {
        float4 a4 = *(const float4*)&A[(size_t)(m0 + ar) * K + k0 + ac];
        As[ac + 0][ar] = a4.x;
        As[ac + 1][ar] = a4.y;
        As[ac + 2][ar] = a4.z;
        As[ac + 3][ar] = a4.w;
        *(float4*)&Bs[br][bc] = *(const float4*)&B[(size_t)(k0 + br) * N + n0 + bc];
        __syncthreads();

#pragma unroll
        for (int k = 0; k < BK; k++) {
            float4 av = *(const float4*)&As[k][ty * 4];
            float4 bv = *(const float4*)&Bs[k][tx * 4];
            acc[0][0] += av.x * bv.x; acc[0][1] += av.x * bv.y;
            acc[0][2] += av.x * bv.z; acc[0][3] += av.x * bv.w;
            acc[1][0] += av.y * bv.x; acc[1][1] += av.y * bv.y;
            acc[1][2] += av.y * bv.z; acc[1][3] += av.y * bv.w;
            acc[2][0] += av.z * bv.x; acc[2][1] += av.z * bv.y;
            acc[2][2] += av.z * bv.z; acc[2][3] += av.z * bv.w;
            acc[3][0] += av.w * bv.x; acc[3][1] += av.w * bv.y;
            acc[3][2] += av.w * bv.z; acc[3][3] += av.w * bv.w;
        }
        __syncthreads();
    }

#pragma unroll
    for (int i = 0; i < 4; i++) {
        float4 r = make_float4(acc[i][0], acc[i][1], acc[i][2], acc[i][3]);
        *(float4*)&C[(size_t)(m0 + ty * 4 + i) * N + n0 + tx * 4] = r;
    }
}

__global__ __launch_bounds__(256) void qkv_gemm(const float* __restrict__ A,
                                                const float* __restrict__ B,
                                                int T)
{
    sgemm_body(A, B, g_qkv, T, QKV_N, HID);
}

__global__ __launch_bounds__(256) void out_gemm(const float* __restrict__ B,
                                                float* __restrict__ C,
                                                int T)
{
    sgemm_body(g_attn, B, C, T, HID, HID);
}

/* ---------------- RMSNorm + RoPE for q and k -----------------------
   q additionally pre-scaled by 1/sqrt(D) (RoPE is linear, so scaling
   before RoPE == scaling after). */
__global__ __launch_bounds__(128) void normrope_kernel(const int* __restrict__ positions,
                                                       const float* __restrict__ q_norm_w,
                                                       const float* __restrict__ k_norm_w,
                                                       int T)
{
    const int t = blockIdx.x;
    const int h = blockIdx.y;            /* 0..NH-1 => q head, else kv head */
    const int d = threadIdx.x;           /* 0..127 */

    const float* src;
    const float* w;
    float* dst;
    float sc;
    if (h < NH) {
        src = g_qkv + (size_t)t * QKV_N + h * D;
        w   = q_norm_w;
        dst = g_q + ((size_t)t * NH + h) * D;
        sc  = 0.08838834764831845f;      /* 1/sqrt(128) */
    } else {
        int hk = h - NH;
        src = g_qkv + (size_t)t * QKV_N + NH * D + hk * D;
        w   = k_norm_w;
        dst = g_k + ((size_t)t * NKV + hk) * D;
        sc  = 1.0f;
    }

    float x = src[d];
    float ss = x * x;
#pragma unroll
    for (int o = 16; o > 0; o >>= 1) ss += __shfl_xor_sync(0xFFFFFFFFu, ss, o);

    __shared__ float red[4];
    __shared__ float s[D];
    if ((d & 31) == 0) red[d >> 5] = ss;
    __syncthreads();
    float var = (red[0] + red[1] + red[2] + red[3]) * (1.0f / (float)D);
    float nx = x * rsqrtf(var + 1e-6f) * w[d];
    s[d] = nx;
    __syncthreads();

    if (d < D / 2) {
        float p = (float)positions[t];
        float inv = (float)(1.0 / pow(1000000.0, (double)d / (double)(D / 2)));
        float ang = p * inv;
        float c = cosf(ang);
        float si = sinf(ang);
        float x1 = s[d];
        float x2 = s[d + D / 2];
        dst[d]         = (x1 * c - x2 * si) * sc;
        dst[d + D / 2] = (x2 * c + x1 * si) * sc;
    }
}

/* ---------------- causal flash attention (fp32, lane-pair split) ----
   Block: 128 threads handle 64 q-rows. Lanes 2r / 2r+1 own the same
   q-row; each lane owns 64 of the 128 head dims (acc = 16 float4).
   Scores are computed as half-dots and combined with shfl_xor(1).
   smem = q(64) + k(32) + v(32) rows  = 67.6 KB -> 3 blocks/SM.       */
#define AT_BM 64
#define AT_BN 32
#define LDW   132   /* padded row stride in floats */

extern __shared__ float s_attn[];

__global__ __launch_bounds__(128, 3) void attn_kernel(int T)
{
    float* qs = s_attn;                 /* 64 x 132 */
    float* ks = qs + AT_BM * LDW;       /* 32 x 132 */
    float* vs = ks + AT_BN * LDW;       /* 32 x 132 */

    const int h   = blockIdx.y;
    const int hk  = h >> 1;                      /* group = NH/NKV = 2 */
    const int bi  = gridDim.x - 1 - blockIdx.x;  /* heavy blocks first */
    const int m0  = bi * AT_BM;
    const int tid = threadIdx.x;
    const int row = tid >> 1;                    /* 0..63 */
    const int hoff = (tid & 1) << 6;             /* 0 or 64 */
    const int qi  = m0 + row;

    /* load q tile (already scaled by 1/sqrt(D)) */
    {
        const int c = tid & 31, r = tid >> 5;
#pragma unroll
        for (int p = 0; p < AT_BM / 4; p++) {
            int rr = r + p * 4;
            *(float4*)&qs[rr * LDW + c * 4] =
                *(const float4*)&g_q[((size_t)(m0 + rr) * NH + h) * D + c * 4];
        }
    }

    float4 acc[16];
#pragma unroll
    for (int u = 0; u < 16; u++) acc[u] = make_float4(0.f, 0.f, 0.f, 0.f);
    float mrow = -1e30f;
    float lrow = 0.f;

    const int ntiles = (m0 + AT_BM) / AT_BN;
    for (int kt = 0; kt < ntiles; kt++) {
        const int k0 = kt * AT_BN;
        __syncthreads();   /* previous tile fully consumed */
        {
            const int c = tid & 31, r = tid >> 5;
#pragma unroll
            for (int p = 0; p < AT_BN / 4; p++) {
                int rr = r + p * 4;
                *(float4*)&ks[rr * LDW + c * 4] =
                    *(const float4*)&g_k[((size_t)(k0 + rr) * NKV + hk) * D + c * 4];
                *(float4*)&vs[rr * LDW + c * 4] =
                    *(const float4*)&g_qkv[(size_t)(k0 + rr) * QKV_N + (NH + NKV) * D + hk * D + c * 4];
            }
        }
        __syncthreads();

        /* half-dot scores over this lane's 64 dims */
        float s[AT_BN];
#pragma unroll
        for (int jj = 0; jj < AT_BN; jj++) s[jj] = 0.f;
#pragma unroll
        for (int c0 = 0; c0 < 64; c0 += 32) {
            float q[32];
#pragma unroll
            for (int u = 0; u < 8; u++) {
                float4 t4 = *(const float4*)&qs[row * LDW + hoff + c0 + u * 4];
                q[4 * u + 0] = t4.x; q[4 * u + 1] = t4.y;
                q[4 * u + 2] = t4.z; q[4 * u + 3] = t4.w;
            }
            for (int jj = 0; jj < AT_BN; jj++) {
                float sj = 0.f;
#pragma unroll
                for (int u = 0; u < 8; u++) {
                    float4 k4 = *(const float4*)&ks[jj * LDW + hoff + c0 + u * 4];
                    sj += q[4 * u + 0] * k4.x + q[4 * u + 1] * k4.y
                        + q[4 * u + 2] * k4.z + q[4 * u + 3] * k4.w;
                }
                s[jj] += sj;
            }
        }

        /* combine half-dots, causal mask, online softmax */
        float mt = mrow;
#pragma unroll
        for (int jj = 0; jj < AT_BN; jj++) {
            s[jj] += __shfl_xor_sync(0xFFFFFFFFu, s[jj], 1);
            if (k0 + jj > qi) s[jj] = -1e30f;
            mt = fmaxf(mt, s[jj]);
        }
        float corr = __expf(mrow - mt);
        mrow = mt;
        float psum = 0.f;
#pragma unroll
        for (int jj = 0; jj < AT_BN; jj++) {
            float pj = __expf(s[jj] - mt);
            s[jj] = pj;
            psum += pj;
        }
        lrow = lrow * corr + psum;

#pragma unroll
        for (int u = 0; u < 16; u++) {
            acc[u].x *= corr; acc[u].y *= corr;
            acc[u].z *= corr; acc[u].w *= corr;
        }
        for (int jj = 0; jj < AT_BN; jj++) {
            float pj = s[jj];
#pragma unroll
            for (int u = 0; u < 16; u++) {
                float4 v4 = *(const float4*)&vs[jj * LDW + hoff + u * 4];
                acc[u].x += pj * v4.x; acc[u].y += pj * v4.y;
                acc[u].z += pj * v4.z; acc[u].w += pj * v4.w;
            }
        }
    }

    const float inv = 1.f / lrow;
#pragma unroll
    for (int u = 0; u < 16; u++) {
        float4 r4 = acc[u];
        r4.x *= inv; r4.y *= inv; r4.z *= inv; r4.w *= inv;
        *(float4*)&g_attn[(size_t)qi * (NH * D) + h * D + hoff + u * 4] = r4;
    }
}

/* ---------------- launch -------------------------------------------- */
extern "C" void kernel_launch(void* const* d_in, const int* in_sizes, int n_in,
                              void* d_out, int out_size)
{
    const int*   positions = (const int*)d_in[0];
    const float* hidden    = (const float*)d_in[1];
    const float* w_qkv     = (const float*)d_in[2];
    const float* q_norm_w  = (const float*)d_in[3];
    const float* k_norm_w  = (const float*)d_in[4];
    const float* w_o       = (const float*)d_in[5];
    float*       out       = (float*)d_out;
    const int    T         = in_sizes[0];   /* 2048 */

    /* 1) QKV projection: [T,HID] @ [HID,4096] */
    dim3 g1(QKV_N / BN, T / BM);
    qkv_gemm<<<g1, 256>>>(hidden, w_qkv, T);

    /* 2) RMSNorm + RoPE for q and k (q pre-scaled) */
    dim3 g2(T, NH + NKV);
    normrope_kernel<<<g2, 128>>>(positions, q_norm_w, k_norm_w, T);

    /* 3) causal GQA flash attention */
    int smem = (AT_BM + 2 * AT_BN) * LDW * (int)sizeof(float);
    cudaFuncSetAttribute(attn_kernel, cudaFuncAttributeMaxDynamicSharedMemorySize, smem);
    dim3 g3(T / AT_BM, NH);
    attn_kernel<<<g3, 128, smem>>>(T);

    /* 4) output projection: [T,2048] @ [2048,2048] */
    dim3 g4(HID / BN, T / BM);
    out_gemm<<<g4, 256>>>(w_o, out, T);
}

// round 4
// speedup vs baseline: 1.4943x; 1.3430x over previous
#include <cuda_runtime.h>
#include <math.h>

#define NH   16
#define NKV  8
#define D    128
#define HID  2048
#define QKV_N ((NH + 2 * NKV) * D)   /* 4096 */
#define MAXT 2048

typedef unsigned long long ull;

/* packed fp32x2 helpers (sm_103a FFMA2) */
#define FMA2(d, a, b) asm("fma.rn.f32x2 %0, %1, %2, %0;" : "+l"(d) : "l"(a), "l"(b))
#define MUL2(d, a, b) asm("mul.rn.f32x2 %0, %1, %2;" : "=l"(d) : "l"(a), "l"(b))
#define PACK2(d, x)   asm("mov.b64 %0, {%1, %1};" : "=l"(d) : "f"(x))
#define UNPACK2(lo, hi, v) asm("mov.b64 {%0, %1}, %2;" : "=f"(lo), "=f"(hi) : "l"(v))

/* ---------------- scratch (no allocations allowed) ---------------- */
__device__ float g_qkv[(size_t)MAXT * QKV_N];       /* 32 MB */
__device__ float g_q  [(size_t)MAXT * NH  * D];     /* 16 MB */
__device__ float g_k  [(size_t)MAXT * NKV * D];     /*  8 MB */
__device__ float g_attn[(size_t)MAXT * NH * D];     /* 16 MB */

/* ---------------- tiled fp32 GEMM (f32x2 inner): C = A @ B --------- */
#define BM 64
#define BN 64
#define BK 16

__device__ __forceinline__ void sgemm_body(const float* __restrict__ A,
                                           const float* __restrict__ B,
                                           float* __restrict__ C,
                                           int M, int N, int K)
{
    __shared__ __align__(16) float As[BK][BM + 4];
    __shared__ __align__(16) float Bs[BK][BN + 4];

    const int tid = threadIdx.x;
    const int tx  = tid & 15;
    const int ty  = tid >> 4;
    const int m0  = blockIdx.y * BM;
    const int n0  = blockIdx.x * BN;

    ull acc2[4][2];
#pragma unroll
    for (int i = 0; i < 4; i++) { acc2[i][0] = 0ull; acc2[i][1] = 0ull; }

    const int ar = tid >> 2;          /* 0..63 */
    const int ac = (tid & 3) << 2;    /* 0,4,8,12 */
    const int br = tid >> 4;          /* 0..15 */
    const int bc = (tid & 15) << 2;   /* 0..60 */

    for (int k0 = 0; k0 < K; k0 += BK) {
        float4 a4 = *(const float4*)&A[(size_t)(m0 + ar) * K + k0 + ac];
        As[ac + 0][ar] = a4.x;
        As[ac + 1][ar] = a4.y;
        As[ac + 2][ar] = a4.z;
        As[ac + 3][ar] = a4.w;
        *(float4*)&Bs[br][bc] = *(const float4*)&B[(size_t)(k0 + br) * N + n0 + bc];
        __syncthreads();

#pragma unroll
        for (int k = 0; k < BK; k++) {
            float4 av = *(const float4*)&As[k][ty * 4];
            ulonglong2 b2 = *(const ulonglong2*)&Bs[k][tx * 4];
            ull a0, a1, a2, a3;
            PACK2(a0, av.x); PACK2(a1, av.y);
            PACK2(a2, av.z); PACK2(a3, av.w);
            FMA2(acc2[0][0], a0, b2.x); FMA2(acc2[0][1], a0, b2.y);
            FMA2(acc2[1][0], a1, b2.x); FMA2(acc2[1][1], a1, b2.y);
            FMA2(acc2[2][0], a2, b2.x); FMA2(acc2[2][1], a2, b2.y);
            FMA2(acc2[3][0], a3, b2.x); FMA2(acc2[3][1], a3, b2.y);
        }
        __syncthreads();
    }

#pragma unroll
    for (int i = 0; i < 4; i++) {
        float c0, c1, c2, c3;
        UNPACK2(c0, c1, acc2[i][0]);
        UNPACK2(c2, c3, acc2[i][1]);
        *(float4*)&C[(size_t)(m0 + ty * 4 + i) * N + n0 + tx * 4] =
            make_float4(c0, c1, c2, c3);
    }
}

__global__ __launch_bounds__(256) void qkv_gemm(const float* __restrict__ A,
                                                const float* __restrict__ B,
                                                int T)
{
    sgemm_body(A, B, g_qkv, T, QKV_N, HID);
}

__global__ __launch_bounds__(256) void out_gemm(const float* __restrict__ B,
                                                float* __restrict__ C,
                                                int T)
{
    sgemm_body(g_attn, B, C, T, HID, HID);
}

/* ---------------- RMSNorm + RoPE for q and k -----------------------
   q additionally pre-scaled by 1/sqrt(D). */
__global__ __launch_bounds__(128) void normrope_kernel(const int* __restrict__ positions,
                                                       const float* __restrict__ q_norm_w,
                                                       const float* __restrict__ k_norm_w,
                                                       int T)
{
    const int t = blockIdx.x;
    const int h = blockIdx.y;
    const int d = threadIdx.x;

    const float* src;
    const float* w;
    float* dst;
    float sc;
    if (h < NH) {
        src = g_qkv + (size_t)t * QKV_N + h * D;
        w   = q_norm_w;
        dst = g_q + ((size_t)t * NH + h) * D;
        sc  = 0.08838834764831845f;
    } else {
        int hk = h - NH;
        src = g_qkv + (size_t)t * QKV_N + NH * D + hk * D;
        w   = k_norm_w;
        dst = g_k + ((size_t)t * NKV + hk) * D;
        sc  = 1.0f;
    }

    float x = src[d];
    float ss = x * x;
#pragma unroll
    for (int o = 16; o > 0; o >>= 1) ss += __shfl_xor_sync(0xFFFFFFFFu, ss, o);

    __shared__ float red[4];
    __shared__ float s[D];
    if ((d & 31) == 0) red[d >> 5] = ss;
    __syncthreads();
    float var = (red[0] + red[1] + red[2] + red[3]) * (1.0f / (float)D);
    float nx = x * rsqrtf(var + 1e-6f) * w[d];
    s[d] = nx;
    __syncthreads();

    if (d < D / 2) {
        float p = (float)positions[t];
        float inv = (float)(1.0 / pow(1000000.0, (double)d / (double)(D / 2)));
        float ang = p * inv;
        float c = cosf(ang);
        float si = sinf(ang);
        float x1 = s[d];
        float x2 = s[d + D / 2];
        dst[d]         = (x1 * c - x2 * si) * sc;
        dst[d + D / 2] = (x2 * c + x1 * si) * sc;
    }
}

/* ---------------- causal flash attention (register-tiled, f32x2) ----
   Block: 128 threads (tx=tid&7, ty=tid>>3), BM=64 q-rows, BN=32 cols.
   S phase: 4x4 microtile (rows 4ty.., cols 4tx..), f32x2 paired over d.
   P -> smem; PV phase: 4 rows x 16 dims (dims tx*16..), f32x2 over dims.
   XOR-swizzled k/q rows and chunk-transposed v for conflict-free LDS. */
#define FBM 64
#define FBN 32
#define LDW 132
#define PLD 33

__global__ __launch_bounds__(128, 2) void attn_kernel(int T_)
{
    extern __shared__ float sm[];
    float* qs = sm;                        /* 64 x 132 */
    float* ks = qs + FBM * LDW;            /* 32 x 132 */
    float* vs = ks + FBN * LDW;            /* 32 x 132 */
    float* ps = vs + FBN * LDW;            /* 64 x 33  */

    const int h   = blockIdx.y;
    const int hk  = h >> 1;
    const int bi  = gridDim.x - 1 - blockIdx.x;   /* heavy blocks first */
    const int m0  = bi * FBM;
    const int tid = threadIdx.x;
    const int tx  = tid & 7;
    const int ty  = tid >> 3;

    /* q fill (pre-scaled by 1/sqrt(D)); row-XOR swizzle on chunk index */
#pragma unroll
    for (int it = 0; it < 16; it++) {
        int idx = tid + it * 128;
        int r = idx >> 5, c = idx & 31;
        *(float4*)&qs[r * LDW + 4 * (c ^ ((r >> 2) & 7))] =
            *(const float4*)&g_q[((size_t)(m0 + r) * NH + h) * D + c * 4];
    }

    ull acc2[4][8];
#pragma unroll
    for (int i = 0; i < 4; i++)
#pragma unroll
        for (int u = 0; u < 8; u++) acc2[i][u] = 0ull;
    float mrow[4] = {-1e30f, -1e30f, -1e30f, -1e30f};
    float lrow[4] = {0.f, 0.f, 0.f, 0.f};

    const int ntiles = (m0 + FBM) / FBN;
    for (int kt = 0; kt < ntiles; kt++) {
        const int k0 = kt * FBN;
        __syncthreads();     /* prev tile's vs/ps fully consumed */

        /* k/v fill: k row-XOR swizzle, v chunk-transpose swizzle */
#pragma unroll
        for (int it = 0; it < 8; it++) {
            int idx = tid + it * 128;
            int r = idx >> 5, c = idx & 31;
            *(float4*)&ks[r * LDW + 4 * (c ^ ((r >> 2) & 7))] =
                *(const float4*)&g_k[((size_t)(k0 + r) * NKV + hk) * D + c * 4];
            *(float4*)&vs[r * LDW + 4 * (((c & 3) << 3) | (c >> 2))] =
                *(const float4*)&g_qkv[(size_t)(k0 + r) * QKV_N + (NH + NKV) * D + hk * D + c * 4];
        }
        __syncthreads();

        /* ---- S = Q K^T (f32x2 accumulate over d-pairs) ---- */
        ull s2[4][4];
#pragma unroll
        for (int i = 0; i < 4; i++)
#pragma unroll
            for (int j = 0; j < 4; j++) s2[i][j] = 0ull;

#pragma unroll 4
        for (int fc = 0; fc < 32; fc++) {
            ulonglong2 qv[4], kv[4];
#pragma unroll
            for (int i = 0; i < 4; i++)
                qv[i] = *(const ulonglong2*)&qs[(4 * ty + i) * LDW + 4 * (fc ^ (ty & 7))];
#pragma unroll
            for (int j = 0; j < 4; j++)
                kv[j] = *(const ulonglong2*)&ks[(4 * tx + j) * LDW + 4 * (fc ^ tx)];
#pragma unroll
            for (int i = 0; i < 4; i++)
#pragma unroll
                for (int j = 0; j < 4; j++) {
                    FMA2(s2[i][j], qv[i].x, kv[j].x);
                    FMA2(s2[i][j], qv[i].y, kv[j].y);
                }
        }

        /* reduce pairs, mask, online softmax */
        float s[4][4];
#pragma unroll
        for (int i = 0; i < 4; i++)
#pragma unroll
            for (int j = 0; j < 4; j++) {
                float lo, hi;
                UNPACK2(lo, hi, s2[i][j]);
                s[i][j] = lo + hi;
            }

        float corr[4];
#pragma unroll
        for (int i = 0; i < 4; i++) {
            const int qi = m0 + 4 * ty + i;
            float mx = mrow[i];
#pragma unroll
            for (int j = 0; j < 4; j++) {
                int col = k0 + 4 * tx + j;
                s[i][j] = (col <= qi) ? s[i][j] : -1e30f;
                mx = fmaxf(mx, s[i][j]);
            }
            mx = fmaxf(mx, __shfl_xor_sync(0xFFFFFFFFu, mx, 1));
            mx = fmaxf(mx, __shfl_xor_sync(0xFFFFFFFFu, mx, 2));
            mx = fmaxf(mx, __shfl_xor_sync(0xFFFFFFFFu, mx, 4));
            corr[i] = __expf(mrow[i] - mx);
            mrow[i] = mx;
            float psum = 0.f;
#pragma unroll
            for (int j = 0; j < 4; j++) {
                float pv = __expf(s[i][j] - mx);
                s[i][j] = pv;
                psum += pv;
            }
            psum += __shfl_xor_sync(0xFFFFFFFFu, psum, 1);
            psum += __shfl_xor_sync(0xFFFFFFFFu, psum, 2);
            psum += __shfl_xor_sync(0xFFFFFFFFu, psum, 4);
            lrow[i] = lrow[i] * corr[i] + psum;
        }

        /* write P tile */
#pragma unroll
        for (int i = 0; i < 4; i++)
#pragma unroll
            for (int j = 0; j < 4; j++)
                ps[(4 * ty + i) * PLD + 4 * tx + j] = s[i][j];

        /* rescale accumulators */
#pragma unroll
        for (int i = 0; i < 4; i++) {
            ull cc;
            PACK2(cc, corr[i]);
#pragma unroll
            for (int u = 0; u < 8; u++) MUL2(acc2[i][u], acc2[i][u], cc);
        }
        __syncthreads();    /* ps visible */

        /* ---- O += P V (f32x2 over dims) ---- */
#pragma unroll 4
        for (int jj = 0; jj < FBN; jj++) {
            ull pp[4];
#pragma unroll
            for (int i = 0; i < 4; i++) {
                float pv = ps[(4 * ty + i) * PLD + jj];
                PACK2(pp[i], pv);
            }
            ulonglong2 vv[4];
#pragma unroll
            for (int u = 0; u < 4; u++)
                vv[u] = *(const ulonglong2*)&vs[jj * LDW + 32 * u + 4 * tx];
#pragma unroll
            for (int i = 0; i < 4; i++)
#pragma unroll
                for (int u = 0; u < 4; u++) {
                    FMA2(acc2[i][2 * u],     pp[i], vv[u].x);
                    FMA2(acc2[i][2 * u + 1], pp[i], vv[u].y);
                }
        }
    }

    /* output: rows 4ty+i, dims tx*16 .. +15 */
#pragma unroll
    for (int i = 0; i < 4; i++) {
        const float inv = 1.f / lrow[i];
        const int qi = m0 + 4 * ty + i;
        float fo[16];
#pragma unroll
        for (int p = 0; p < 8; p++) UNPACK2(fo[2 * p], fo[2 * p + 1], acc2[i][p]);
#pragma unroll
        for (int u = 0; u < 4; u++) {
            float4 r = make_float4(fo[4 * u + 0] * inv, fo[4 * u + 1] * inv,
                                   fo[4 * u + 2] * inv, fo[4 * u + 3] * inv);
            *(float4*)&g_attn[(size_t)qi * (NH * D) + h * D + tx * 16 + u * 4] = r;
        }
    }
}

/* ---------------- launch -------------------------------------------- */
extern "C" void kernel_launch(void* const* d_in, const int* in_sizes, int n_in,
                              void* d_out, int out_size)
{
    const int*   positions = (const int*)d_in[0];
    const float* hidden    = (const float*)d_in[1];
    const float* w_qkv     = (const float*)d_in[2];
    const float* q_norm_w  = (const float*)d_in[3];
    const float* k_norm_w  = (const float*)d_in[4];
    const float* w_o       = (const float*)d_in[5];
    float*       out       = (float*)d_out;
    const int    T         = in_sizes[0];   /* 2048 */

    /* 1) QKV projection */
    dim3 g1(QKV_N / BN, T / BM);
    qkv_gemm<<<g1, 256>>>(hidden, w_qkv, T);

    /* 2) RMSNorm + RoPE */
    dim3 g2(T, NH + NKV);
    normrope_kernel<<<g2, 128>>>(positions, q_norm_w, k_norm_w, T);

    /* 3) causal GQA flash attention */
    int smem = (FBM + 2 * FBN) * LDW * (int)sizeof(float) + FBM * PLD * (int)sizeof(float);
    cudaFuncSetAttribute(attn_kernel, cudaFuncAttributeMaxDynamicSharedMemorySize, smem);
    dim3 g3(T / FBM, NH);
    attn_kernel<<<g3, 128, smem>>>(T);

    /* 4) output projection */
    dim3 g4(HID / BN, T / BM);
    out_gemm<<<g4, 256>>>(w_o, out, T);
}

// round 7
// speedup vs baseline: 1.5519x; 1.0386x over previous
#include <cuda_runtime.h>
#include <cuda_bf16.h>
#include <stdint.h>
#include <math.h>

#define NH   16
#define NKV  8
#define D    128
#define HID  2048
#define QKV_N ((NH + 2 * NKV) * D)   /* 4096 */
#define MAXT 2048

typedef unsigned long long ull;

/* packed fp32x2 helpers (used by attention) */
#define FMA2(d, a, b) asm("fma.rn.f32x2 %0, %1, %2, %0;" : "+l"(d) : "l"(a), "l"(b))
#define MUL2(d, a, b) asm("mul.rn.f32x2 %0, %1, %2;" : "=l"(d) : "l"(a), "l"(b))
#define PACK2(d, x)   asm("mov.b64 %0, {%1, %1};" : "=l"(d) : "f"(x))
#define UNPACK2(lo, hi, v) asm("mov.b64 {%0, %1}, %2;" : "=f"(lo), "=f"(hi) : "l"(v))

/* ---------------- scratch (no allocations allowed) ---------------- */
__device__ float g_qkv [(size_t)MAXT * QKV_N];
__device__ float g_q   [(size_t)MAXT * NH  * D];
__device__ float g_k   [(size_t)MAXT * NKV * D];
__device__ float g_attn[(size_t)MAXT * NH * D];

/* split-bf16 operands */
__device__ __nv_bfloat16 g_ah  [(size_t)MAXT * HID];
__device__ __nv_bfloat16 g_al  [(size_t)MAXT * HID];
__device__ __nv_bfloat16 g_wqt_h[(size_t)QKV_N * HID];
__device__ __nv_bfloat16 g_wqt_l[(size_t)QKV_N * HID];
__device__ __nv_bfloat16 g_oth [(size_t)MAXT * NH * D];
__device__ __nv_bfloat16 g_otl [(size_t)MAXT * NH * D];
__device__ __nv_bfloat16 g_wot_h[(size_t)HID * HID];
__device__ __nv_bfloat16 g_wot_l[(size_t)HID * HID];

/* ================= mma.sync helpers ================================ */
__device__ __forceinline__ uint32_t smem_u32(const void* p) {
    uint32_t a;
    asm("{ .reg .u64 t; cvta.to.shared.u64 t, %1; cvt.u32.u64 %0, t; }"
        : "=r"(a) : "l"(p));
    return a;
}

#define LDSM_X4(r0, r1, r2, r3, addr)                                          \
    asm volatile("ldmatrix.sync.aligned.m8n8.x4.shared.b16 {%0,%1,%2,%3}, [%4];" \
        : "=r"(r0), "=r"(r1), "=r"(r2), "=r"(r3) : "r"(addr))

#define MMA16816(d, a0, a1, a2, a3, b0, b1)                                    \
    asm volatile("mma.sync.aligned.m16n8k16.row.col.f32.bf16.bf16.f32 "        \
        "{%0,%1,%2,%3}, {%4,%5,%6,%7}, {%8,%9}, {%0,%1,%2,%3};"                \
        : "+f"((d)[0]), "+f"((d)[1]), "+f"((d)[2]), "+f"((d)[3])               \
        : "r"(a0), "r"(a1), "r"(a2), "r"(a3), "r"(b0), "r"(b1))

/* ================= split-bf16 tensor GEMM ==========================
   C[M,N] fp32 = (Ah+Al)[M,K] @ (Bh+Bl)[N,K]^T, dropping Al*Bl.
   CTA 128x128, K-chunk 64, double-buffered smem, 8 warps (64x32 each).
   smem tile layout: row r (128B) at r*128, 16B seg s at (s^(r&7))*16. */
#define KC      64
#define TILE_B  (128 * 128)            /* bytes per tile (128 rows x 128B) */
#define STAGE_B (4 * TILE_B)           /* Ah, Al, Bh, Bl */
#define GSM_TOTAL (2 * STAGE_B)

__device__ __forceinline__ void load_tiles(char* smem, int st,
    const __nv_bfloat16* Ah, const __nv_bfloat16* Al,
    const __nv_bfloat16* Bh, const __nv_bfloat16* Bl,
    int m0, int n0, int K, int k0)
{
    char* base = smem + st * STAGE_B;
    const int tid = threadIdx.x;
    const __nv_bfloat16* srcs[4] = {Ah, Al, Bh, Bl};
#pragma unroll
    for (int it = 0; it < 16; it++) {
        int gidx = tid + it * 256;         /* 0..4095 */
        int tile = gidx >> 10;
        int r    = (gidx >> 3) & 127;
        int s    = gidx & 7;
        int row0 = (tile < 2) ? m0 : n0;
        const __nv_bfloat16* src = srcs[tile];
        float4 v = *(const float4*)(src + (size_t)(row0 + r) * K + k0 + s * 8);
        *(float4*)(base + tile * TILE_B + r * 128 + ((s ^ (r & 7)) << 4)) = v;
    }
}

__global__ __launch_bounds__(256, 1) void tc_gemm(
    const __nv_bfloat16* __restrict__ Ah, const __nv_bfloat16* __restrict__ Al,
    const __nv_bfloat16* __restrict__ Bh, const __nv_bfloat16* __restrict__ Bl,
    float* __restrict__ C, int M, int N, int K)
{
    extern __shared__ char smem[];
    const int tid = threadIdx.x;
    const int wid = tid >> 5;
    const int lid = tid & 31;
    const int mw  = wid & 1;           /* 2 warps over M  */
    const int nw  = wid >> 1;          /* 4 warps over N  */
    const int m0  = blockIdx.y * 128;
    const int n0  = blockIdx.x * 128;

    const uint32_t sb = smem_u32(smem);

    float acc[4][4][4];                /* [mf][n8][regs] */
#pragma unroll
    for (int i = 0; i < 4; i++)
#pragma unroll
        for (int j = 0; j < 4; j++)
#pragma unroll
            for (int u = 0; u < 4; u++) acc[i][j][u] = 0.f;

    load_tiles(smem, 0, Ah, Al, Bh, Bl, m0, n0, K, 0);
    __syncthreads();

    const int nch = K / KC;
    for (int c = 0; c < nch; c++) {
        const int st = c & 1;
        if (c + 1 < nch)
            load_tiles(smem, st ^ 1, Ah, Al, Bh, Bl, m0, n0, K, (c + 1) * KC);

        const uint32_t tAh = sb + st * STAGE_B + 0 * TILE_B;
        const uint32_t tAl = sb + st * STAGE_B + 1 * TILE_B;
        const uint32_t tBh = sb + st * STAGE_B + 2 * TILE_B;
        const uint32_t tBl = sb + st * STAGE_B + 3 * TILE_B;

#pragma unroll
        for (int kb = 0; kb < KC / 16; kb++) {
            /* fragment smem addresses (16B-granular, seg^row swizzle) */
            uint32_t ah[4][4], al[4][4];
#pragma unroll
            for (int mf = 0; mf < 4; mf++) {
                int r = mw * 64 + mf * 16 + (lid & 15);
                int s = 2 * kb + (lid >> 4);
                uint32_t off = (uint32_t)(r * 128 + ((s ^ (r & 7)) << 4));
                LDSM_X4(ah[mf][0], ah[mf][1], ah[mf][2], ah[mf][3], tAh + off);
                LDSM_X4(al[mf][0], al[mf][1], al[mf][2], al[mf][3], tAl + off);
            }
            uint32_t bh[4][2], bl[4][2];
#pragma unroll
            for (int nb = 0; nb < 2; nb++) {
                int r = nw * 32 + nb * 16 + (lid & 15);
                int s = 2 * kb + (lid >> 4);
                uint32_t off = (uint32_t)(r * 128 + ((s ^ (r & 7)) << 4));
                uint32_t r0, r1, r2, r3;
                LDSM_X4(r0, r1, r2, r3, tBh + off);
                bh[2 * nb + 0][0] = r0; bh[2 * nb + 0][1] = r2;
                bh[2 * nb + 1][0] = r1; bh[2 * nb + 1][1] = r3;
                LDSM_X4(r0, r1, r2, r3, tBl + off);
                bl[2 * nb + 0][0] = r0; bl[2 * nb + 0][1] = r2;
                bl[2 * nb + 1][0] = r1; bl[2 * nb + 1][1] = r3;
            }
#pragma unroll
            for (int mf = 0; mf < 4; mf++)
#pragma unroll
                for (int j = 0; j < 4; j++) {
                    MMA16816(acc[mf][j], ah[mf][0], ah[mf][1], ah[mf][2], ah[mf][3],
                             bh[j][0], bh[j][1]);
                    MMA16816(acc[mf][j], ah[mf][0], ah[mf][1], ah[mf][2], ah[mf][3],
                             bl[j][0], bl[j][1]);
                    MMA16816(acc[mf][j], al[mf][0], al[mf][1], al[mf][2], al[mf][3],
                             bh[j][0], bh[j][1]);
                }
        }
        __syncthreads();
    }

    /* epilogue: lane l holds rows l/4 and l/4+8, cols 2(l%4), +1 */
#pragma unroll
    for (int mf = 0; mf < 4; mf++) {
        int rbase = m0 + mw * 64 + mf * 16 + (lid >> 2);
#pragma unroll
        for (int j = 0; j < 4; j++) {
            int col = n0 + nw * 32 + j * 8 + 2 * (lid & 3);
            *(float2*)&C[(size_t)rbase * N + col] =
                make_float2(acc[mf][j][0], acc[mf][j][1]);
            *(float2*)&C[(size_t)(rbase + 8) * N + col] =
                make_float2(acc[mf][j][2], acc[mf][j][3]);
        }
    }
}

/* ================= split conversion kernels ======================== */
__global__ __launch_bounds__(256) void cvt_split(const float* __restrict__ x,
                                                 __nv_bfloat16* __restrict__ h,
                                                 __nv_bfloat16* __restrict__ l,
                                                 int n)
{
    int i = (blockIdx.x * 256 + threadIdx.x) * 4;
    if (i >= n) return;
    float4 v = *(const float4*)(x + i);
    float vv[4] = {v.x, v.y, v.z, v.w};
    __nv_bfloat16 hh[4], ll[4];
#pragma unroll
    for (int j = 0; j < 4; j++) {
        hh[j] = __float2bfloat16(vv[j]);
        ll[j] = __float2bfloat16(vv[j] - __bfloat162float(hh[j]));
    }
    *(uint2*)(h + i) = *(uint2*)hh;
    *(uint2*)(l + i) = *(uint2*)ll;
}

/* transpose + split: x[R,C] fp32 -> th,tl[C,R] bf16 */
__global__ void cvt_split_t(const float* __restrict__ x,
                            __nv_bfloat16* __restrict__ th,
                            __nv_bfloat16* __restrict__ tl,
                            int R, int C)
{
    __shared__ float t[32][33];
    const int bx = blockIdx.x * 32;   /* over C */
    const int by = blockIdx.y * 32;   /* over R */
    const int tx = threadIdx.x, ty = threadIdx.y;
#pragma unroll
    for (int j = 0; j < 32; j += 8)
        t[ty + j][tx] = x[(size_t)(by + ty + j) * C + bx + tx];
    __syncthreads();
#pragma unroll
    for (int j = 0; j < 32; j += 8) {
        float v = t[tx][ty + j];
        __nv_bfloat16 hh = __float2bfloat16(v);
        float lo = v - __bfloat162float(hh);
        size_t o = (size_t)(bx + ty + j) * R + by + tx;
        th[o] = hh;
        tl[o] = __float2bfloat16(lo);
    }
}

/* ---------------- RMSNorm + RoPE for q and k ----------------------- */
__global__ __launch_bounds__(128) void normrope_kernel(const int* __restrict__ positions,
                                                       const float* __restrict__ q_norm_w,
                                                       const float* __restrict__ k_norm_w,
                                                       int T)
{
    const int t = blockIdx.x;
    const int h = blockIdx.y;
    const int d = threadIdx.x;

    const float* src;
    const float* w;
    float* dst;
    float sc;
    if (h < NH) {
        src = g_qkv + (size_t)t * QKV_N + h * D;
        w   = q_norm_w;
        dst = g_q + ((size_t)t * NH + h) * D;
        sc  = 0.08838834764831845f;
    } else {
        int hk = h - NH;
        src = g_qkv + (size_t)t * QKV_N + NH * D + hk * D;
        w   = k_norm_w;
        dst = g_k + ((size_t)t * NKV + hk) * D;
        sc  = 1.0f;
    }

    float x = src[d];
    float ss = x * x;
#pragma unroll
    for (int o = 16; o > 0; o >>= 1) ss += __shfl_xor_sync(0xFFFFFFFFu, ss, o);

    __shared__ float red[4];
    __shared__ float s[D];
    if ((d & 31) == 0) red[d >> 5] = ss;
    __syncthreads();
    float var = (red[0] + red[1] + red[2] + red[3]) * (1.0f / (float)D);
    float nx = x * rsqrtf(var + 1e-6f) * w[d];
    s[d] = nx;
    __syncthreads();

    if (d < D / 2) {
        float p = (float)positions[t];
        float inv = (float)(1.0 / pow(1000000.0, (double)d / (double)(D / 2)));
        float ang = p * inv;
        float c = cosf(ang);
        float si = sinf(ang);
        float x1 = s[d];
        float x2 = s[d + D / 2];
        dst[d]         = (x1 * c - x2 * si) * sc;
        dst[d + D / 2] = (x2 * c + x1 * si) * sc;
    }
}

/* ---------------- causal flash attention (register-tiled, f32x2) ---- */
#define FBM 64
#define FBN 32
#define LDW 132
#define PLD 33

__global__ __launch_bounds__(128, 2) void attn_kernel(int T_)
{
    extern __shared__ float sm[];
    float* qs = sm;
    float* ks = qs + FBM * LDW;
    float* vs = ks + FBN * LDW;
    float* ps = vs + FBN * LDW;

    const int h   = blockIdx.y;
    const int hk  = h >> 1;
    const int bi  = gridDim.x - 1 - blockIdx.x;
    const int m0  = bi * FBM;
    const int tid = threadIdx.x;
    const int tx  = tid & 7;
    const int ty  = tid >> 3;

#pragma unroll
    for (int it = 0; it < 16; it++) {
        int idx = tid + it * 128;
        int r = idx >> 5, c = idx & 31;
        *(float4*)&qs[r * LDW + 4 * (c ^ ((r >> 2) & 7))] =
            *(const float4*)&g_q[((size_t)(m0 + r) * NH + h) * D + c * 4];
    }

    ull acc2[4][8];
#pragma unroll
    for (int i = 0; i < 4; i++)
#pragma unroll
        for (int u = 0; u < 8; u++) acc2[i][u] = 0ull;
    float mrow[4] = {-1e30f, -1e30f, -1e30f, -1e30f};
    float lrow[4] = {0.f, 0.f, 0.f, 0.f};

    const int ntiles = (m0 + FBM) / FBN;
    for (int kt = 0; kt < ntiles; kt++) {
        const int k0 = kt * FBN;
        __syncthreads();
#pragma unroll
        for (int it = 0; it < 8; it++) {
            int idx = tid + it * 128;
            int r = idx >> 5, c = idx & 31;
            *(float4*)&ks[r * LDW + 4 * (c ^ ((r >> 2) & 7))] =
                *(const float4*)&g_k[((size_t)(k0 + r) * NKV + hk) * D + c * 4];
            *(float4*)&vs[r * LDW + 4 * (((c & 3) << 3) | (c >> 2))] =
                *(const float4*)&g_qkv[(size_t)(k0 + r) * QKV_N + (NH + NKV) * D + hk * D + c * 4];
        }
        __syncthreads();

        ull s2[4][4];
#pragma unroll
        for (int i = 0; i < 4; i++)
#pragma unroll
            for (int j = 0; j < 4; j++) s2[i][j] = 0ull;

#pragma unroll 4
        for (int fc = 0; fc < 32; fc++) {
            ulonglong2 qv[4], kv[4];
#pragma unroll
            for (int i = 0; i < 4; i++)
                qv[i] = *(const ulonglong2*)&qs[(4 * ty + i) * LDW + 4 * (fc ^ (ty & 7))];
#pragma unroll
            for (int j = 0; j < 4; j++)
                kv[j] = *(const ulonglong2*)&ks[(4 * tx + j) * LDW + 4 * (fc ^ tx)];
#pragma unroll
            for (int i = 0; i < 4; i++)
#pragma unroll
                for (int j = 0; j < 4; j++) {
                    FMA2(s2[i][j], qv[i].x, kv[j].x);
                    FMA2(s2[i][j], qv[i].y, kv[j].y);
                }
        }

        float s[4][4];
#pragma unroll
        for (int i = 0; i < 4; i++)
#pragma unroll
            for (int j = 0; j < 4; j++) {
                float lo, hi;
                UNPACK2(lo, hi, s2[i][j]);
                s[i][j] = lo + hi;
            }

        float corr[4];
#pragma unroll
        for (int i = 0; i < 4; i++) {
            const int qi = m0 + 4 * ty + i;
            float mx = mrow[i];
#pragma unroll
            for (int j = 0; j < 4; j++) {
                int col = k0 + 4 * tx + j;
                s[i][j] = (col <= qi) ? s[i][j] : -1e30f;
                mx = fmaxf(mx, s[i][j]);
            }
            mx = fmaxf(mx, __shfl_xor_sync(0xFFFFFFFFu, mx, 1));
            mx = fmaxf(mx, __shfl_xor_sync(0xFFFFFFFFu, mx, 2));
            mx = fmaxf(mx, __shfl_xor_sync(0xFFFFFFFFu, mx, 4));
            corr[i] = __expf(mrow[i] - mx);
            mrow[i] = mx;
            float psum = 0.f;
#pragma unroll
            for (int j = 0; j < 4; j++) {
                float pv = __expf(s[i][j] - mx);
                s[i][j] = pv;
                psum += pv;
            }
            psum += __shfl_xor_sync(0xFFFFFFFFu, psum, 1);
            psum += __shfl_xor_sync(0xFFFFFFFFu, psum, 2);
            psum += __shfl_xor_sync(0xFFFFFFFFu, psum, 4);
            lrow[i] = lrow[i] * corr[i] + psum;
        }

#pragma unroll
        for (int i = 0; i < 4; i++)
#pragma unroll
            for (int j = 0; j < 4; j++)
                ps[(4 * ty + i) * PLD + 4 * tx + j] = s[i][j];

#pragma unroll
        for (int i = 0; i < 4; i++) {
            ull cc;
            PACK2(cc, corr[i]);
#pragma unroll
            for (int u = 0; u < 8; u++) MUL2(acc2[i][u], acc2[i][u], cc);
        }
        __syncthreads();

#pragma unroll 4
        for (int jj = 0; jj < FBN; jj++) {
            ull pp[4];
#pragma unroll
            for (int i = 0; i < 4; i++) {
                float pv = ps[(4 * ty + i) * PLD + jj];
                PACK2(pp[i], pv);
            }
            ulonglong2 vv[4];
#pragma unroll
            for (int u = 0; u < 4; u++)
                vv[u] = *(const ulonglong2*)&vs[jj * LDW + 32 * u + 4 * tx];
#pragma unroll
            for (int i = 0; i < 4; i++)
#pragma unroll
                for (int u = 0; u < 4; u++) {
                    FMA2(acc2[i][2 * u],     pp[i], vv[u].x);
                    FMA2(acc2[i][2 * u + 1], pp[i], vv[u].y);
                }
        }
    }

#pragma unroll
    for (int i = 0; i < 4; i++) {
        const float inv = 1.f / lrow[i];
        const int qi = m0 + 4 * ty + i;
        float fo[16];
#pragma unroll
        for (int p = 0; p < 8; p++) UNPACK2(fo[2 * p], fo[2 * p + 1], acc2[i][p]);
#pragma unroll
        for (int u = 0; u < 4; u++) {
            float4 r = make_float4(fo[4 * u + 0] * inv, fo[4 * u + 1] * inv,
                                   fo[4 * u + 2] * inv, fo[4 * u + 3] * inv);
            *(float4*)&g_attn[(size_t)qi * (NH * D) + h * D + tx * 16 + u * 4] = r;
        }
    }
}

/* ---------------- launch -------------------------------------------- */
extern "C" void kernel_launch(void* const* d_in, const int* in_sizes, int n_in,
                              void* d_out, int out_size)
{
    const int*   positions = (const int*)d_in[0];
    const float* hidden    = (const float*)d_in[1];
    const float* w_qkv     = (const float*)d_in[2];
    const float* q_norm_w  = (const float*)d_in[3];
    const float* k_norm_w  = (const float*)d_in[4];
    const float* w_o       = (const float*)d_in[5];
    float*       out       = (float*)d_out;
    const int    T         = in_sizes[0];   /* 2048 */

    __nv_bfloat16 *ah, *al, *wqh, *wql, *oh, *ol, *woh, *wol;
    cudaGetSymbolAddress((void**)&ah,  g_ah);
    cudaGetSymbolAddress((void**)&al,  g_al);
    cudaGetSymbolAddress((void**)&wqh, g_wqt_h);
    cudaGetSymbolAddress((void**)&wql, g_wqt_l);
    cudaGetSymbolAddress((void**)&oh,  g_oth);
    cudaGetSymbolAddress((void**)&ol,  g_otl);
    cudaGetSymbolAddress((void**)&woh, g_wot_h);
    cudaGetSymbolAddress((void**)&wol, g_wot_l);

    cudaFuncSetAttribute(tc_gemm, cudaFuncAttributeMaxDynamicSharedMemorySize, GSM_TOTAL);

    /* 0) split inputs to compensated bf16 */
    cvt_split<<<(T * HID) / 1024, 256>>>(hidden, ah, al, T * HID);
    cvt_split_t<<<dim3(QKV_N / 32, HID / 32), dim3(32, 8)>>>(w_qkv, wqh, wql, HID, QKV_N);

    /* 1) QKV projection: [T,HID] @ [HID,QKV_N] via tensor cores */
    {
        float* cq;
        cudaGetSymbolAddress((void**)&cq, g_qkv);
        dim3 g(QKV_N / 128, T / 128);
        tc_gemm<<<g, 256, GSM_TOTAL>>>(ah, al, wqh, wql, cq, T, QKV_N, HID);
    }

    /* 2) RMSNorm + RoPE */
    dim3 g2(T, NH + NKV);
    normrope_kernel<<<g2, 128>>>(positions, q_norm_w, k_norm_w, T);

    /* 3) causal GQA flash attention (fp32) */
    int smem = (FBM + 2 * FBN) * LDW * (int)sizeof(float) + FBM * PLD * (int)sizeof(float);
    cudaFuncSetAttribute(attn_kernel, cudaFuncAttributeMaxDynamicSharedMemorySize, smem);
    dim3 g3(T / FBM, NH);
    attn_kernel<<<g3, 128, smem>>>(T);

    /* 4) split attn output + w_o, then output projection */
    {
        float* ap;
        cudaGetSymbolAddress((void**)&ap, g_attn);
        cvt_split<<<(T * NH * D) / 1024, 256>>>(ap, oh, ol, T * NH * D);
    }
    cvt_split_t<<<dim3(HID / 32, (NH * D) / 32), dim3(32, 8)>>>(w_o, woh, wol, NH * D, HID);
    {
        dim3 g(HID / 128, T / 128);
        tc_gemm<<<g, 256, GSM_TOTAL>>>(oh, ol, woh, wol, out, T, HID, HID);
    }
}

// round 8
// speedup vs baseline: 2.3746x; 1.5301x over previous
#include <cuda_runtime.h>
#include <cuda_bf16.h>
#include <stdint.h>
#include <math.h>

#define NH   16
#define NKV  8
#define D    128
#define HID  2048
#define QKV_N ((NH + 2 * NKV) * D)   /* 4096 */
#define MAXT 2048

/* ---------------- scratch (no allocations allowed) ---------------- */
__device__ float g_qkv [(size_t)MAXT * QKV_N];
__device__ float g_invfreq[D / 2];

/* split-bf16 operands */
__device__ __nv_bfloat16 g_ah  [(size_t)MAXT * HID];
__device__ __nv_bfloat16 g_al  [(size_t)MAXT * HID];
__device__ __nv_bfloat16 g_wqt_h[(size_t)QKV_N * HID];
__device__ __nv_bfloat16 g_wqt_l[(size_t)QKV_N * HID];
__device__ __nv_bfloat16 g_wot_h[(size_t)HID * HID];
__device__ __nv_bfloat16 g_wot_l[(size_t)HID * HID];

/* attention operands / outputs (all compensated bf16 splits) */
__device__ __nv_bfloat16 g_qh[(size_t)MAXT * NH  * D];
__device__ __nv_bfloat16 g_ql[(size_t)MAXT * NH  * D];
__device__ __nv_bfloat16 g_kh[(size_t)MAXT * NKV * D];
__device__ __nv_bfloat16 g_kl[(size_t)MAXT * NKV * D];
__device__ __nv_bfloat16 g_vh[(size_t)MAXT * NKV * D];
__device__ __nv_bfloat16 g_vl[(size_t)MAXT * NKV * D];
__device__ __nv_bfloat16 g_oth[(size_t)MAXT * NH * D];
__device__ __nv_bfloat16 g_otl[(size_t)MAXT * NH * D];

/* ================= mma.sync helpers ================================ */
__device__ __forceinline__ uint32_t smem_u32(const void* p) {
    uint32_t a;
    asm("{ .reg .u64 t; cvta.to.shared.u64 t, %1; cvt.u32.u64 %0, t; }"
        : "=r"(a) : "l"(p));
    return a;
}

#define LDSM_X4(r0, r1, r2, r3, addr)                                          \
    asm volatile("ldmatrix.sync.aligned.m8n8.x4.shared.b16 {%0,%1,%2,%3}, [%4];" \
        : "=r"(r0), "=r"(r1), "=r"(r2), "=r"(r3) : "r"(addr))

#define LDSM_X4_T(r0, r1, r2, r3, addr)                                        \
    asm volatile("ldmatrix.sync.aligned.m8n8.x4.trans.shared.b16 {%0,%1,%2,%3}, [%4];" \
        : "=r"(r0), "=r"(r1), "=r"(r2), "=r"(r3) : "r"(addr))

#define MMA16816(d, a0, a1, a2, a3, b0, b1)                                    \
    asm volatile("mma.sync.aligned.m16n8k16.row.col.f32.bf16.bf16.f32 "        \
        "{%0,%1,%2,%3}, {%4,%5,%6,%7}, {%8,%9}, {%0,%1,%2,%3};"                \
        : "+f"((d)[0]), "+f"((d)[1]), "+f"((d)[2]), "+f"((d)[3])               \
        : "r"(a0), "r"(a1), "r"(a2), "r"(a3), "r"(b0), "r"(b1))

/* pack two fp32 -> bf16x2 (lo in low half) */
__device__ __forceinline__ uint32_t packbf(float lo, float hi) {
    uint32_t r;
    asm("cvt.rn.bf16x2.f32 %0, %1, %2;" : "=r"(r) : "f"(hi), "f"(lo));
    return r;
}

/* ================= split-bf16 tensor GEMM (unchanged, passing) ===== */
#define KC      64
#define TILE_B  (128 * 128)
#define STAGE_B (4 * TILE_B)
#define GSM_TOTAL (2 * STAGE_B)

__device__ __forceinline__ void load_tiles(char* smem, int st,
    const __nv_bfloat16* Ah, const __nv_bfloat16* Al,
    const __nv_bfloat16* Bh, const __nv_bfloat16* Bl,
    int m0, int n0, int K, int k0)
{
    char* base = smem + st * STAGE_B;
    const int tid = threadIdx.x;
    const __nv_bfloat16* srcs[4] = {Ah, Al, Bh, Bl};
#pragma unroll
    for (int it = 0; it < 16; it++) {
        int gidx = tid + it * 256;
        int tile = gidx >> 10;
        int r    = (gidx >> 3) & 127;
        int s    = gidx & 7;
        int row0 = (tile < 2) ? m0 : n0;
        const __nv_bfloat16* src = srcs[tile];
        float4 v = *(const float4*)(src + (size_t)(row0 + r) * K + k0 + s * 8);
        *(float4*)(base + tile * TILE_B + r * 128 + ((s ^ (r & 7)) << 4)) = v;
    }
}

__global__ __launch_bounds__(256, 1) void tc_gemm(
    const __nv_bfloat16* __restrict__ Ah, const __nv_bfloat16* __restrict__ Al,
    const __nv_bfloat16* __restrict__ Bh, const __nv_bfloat16* __restrict__ Bl,
    float* __restrict__ C, int M, int N, int K)
{
    extern __shared__ char smem[];
    const int tid = threadIdx.x;
    const int wid = tid >> 5;
    const int lid = tid & 31;
    const int mw  = wid & 1;
    const int nw  = wid >> 1;
    const int m0  = blockIdx.y * 128;
    const int n0  = blockIdx.x * 128;

    const uint32_t sb = smem_u32(smem);

    float acc[4][4][4];
#pragma unroll
    for (int i = 0; i < 4; i++)
#pragma unroll
        for (int j = 0; j < 4; j++)
#pragma unroll
            for (int u = 0; u < 4; u++) acc[i][j][u] = 0.f;

    load_tiles(smem, 0, Ah, Al, Bh, Bl, m0, n0, K, 0);
    __syncthreads();

    const int nch = K / KC;
    for (int c = 0; c < nch; c++) {
        const int st = c & 1;
        if (c + 1 < nch)
            load_tiles(smem, st ^ 1, Ah, Al, Bh, Bl, m0, n0, K, (c + 1) * KC);

        const uint32_t tAh = sb + st * STAGE_B + 0 * TILE_B;
        const uint32_t tAl = sb + st * STAGE_B + 1 * TILE_B;
        const uint32_t tBh = sb + st * STAGE_B + 2 * TILE_B;
        const uint32_t tBl = sb + st * STAGE_B + 3 * TILE_B;

#pragma unroll
        for (int kb = 0; kb < KC / 16; kb++) {
            uint32_t ah[4][4], al[4][4];
#pragma unroll
            for (int mf = 0; mf < 4; mf++) {
                int r = mw * 64 + mf * 16 + (lid & 15);
                int s = 2 * kb + (lid >> 4);
                uint32_t off = (uint32_t)(r * 128 + ((s ^ (r & 7)) << 4));
                LDSM_X4(ah[mf][0], ah[mf][1], ah[mf][2], ah[mf][3], tAh + off);
                LDSM_X4(al[mf][0], al[mf][1], al[mf][2], al[mf][3], tAl + off);
            }
            uint32_t bh[4][2], bl[4][2];
#pragma unroll
            for (int nb = 0; nb < 2; nb++) {
                int r = nw * 32 + nb * 16 + (lid & 15);
                int s = 2 * kb + (lid >> 4);
                uint32_t off = (uint32_t)(r * 128 + ((s ^ (r & 7)) << 4));
                uint32_t r0, r1, r2, r3;
                LDSM_X4(r0, r1, r2, r3, tBh + off);
                bh[2 * nb + 0][0] = r0; bh[2 * nb + 0][1] = r2;
                bh[2 * nb + 1][0] = r1; bh[2 * nb + 1][1] = r3;
                LDSM_X4(r0, r1, r2, r3, tBl + off);
                bl[2 * nb + 0][0] = r0; bl[2 * nb + 0][1] = r2;
                bl[2 * nb + 1][0] = r1; bl[2 * nb + 1][1] = r3;
            }
#pragma unroll
            for (int mf = 0; mf < 4; mf++)
#pragma unroll
                for (int j = 0; j < 4; j++) {
                    MMA16816(acc[mf][j], ah[mf][0], ah[mf][1], ah[mf][2], ah[mf][3],
                             bh[j][0], bh[j][1]);
                    MMA16816(acc[mf][j], ah[mf][0], ah[mf][1], ah[mf][2], ah[mf][3],
                             bl[j][0], bl[j][1]);
                    MMA16816(acc[mf][j], al[mf][0], al[mf][1], al[mf][2], al[mf][3],
                             bh[j][0], bh[j][1]);
                }
        }
        __syncthreads();
    }

#pragma unroll
    for (int mf = 0; mf < 4; mf++) {
        int rbase = m0 + mw * 64 + mf * 16 + (lid >> 2);
#pragma unroll
        for (int j = 0; j < 4; j++) {
            int col = n0 + nw * 32 + j * 8 + 2 * (lid & 3);
            *(float2*)&C[(size_t)rbase * N + col] =
                make_float2(acc[mf][j][0], acc[mf][j][1]);
            *(float2*)&C[(size_t)(rbase + 8) * N + col] =
                make_float2(acc[mf][j][2], acc[mf][j][3]);
        }
    }
}

/* ================= split conversion kernels ======================== */
__global__ __launch_bounds__(256) void cvt_split(const float* __restrict__ x,
                                                 __nv_bfloat16* __restrict__ h,
                                                 __nv_bfloat16* __restrict__ l,
                                                 int n)
{
    int i = (blockIdx.x * 256 + threadIdx.x) * 4;
    if (i >= n) return;
    float4 v = *(const float4*)(x + i);
    float vv[4] = {v.x, v.y, v.z, v.w};
    __nv_bfloat16 hh[4], ll[4];
#pragma unroll
    for (int j = 0; j < 4; j++) {
        hh[j] = __float2bfloat16(vv[j]);
        ll[j] = __float2bfloat16(vv[j] - __bfloat162float(hh[j]));
    }
    *(uint2*)(h + i) = *(uint2*)hh;
    *(uint2*)(l + i) = *(uint2*)ll;
}

__global__ void cvt_split_t(const float* __restrict__ x,
                            __nv_bfloat16* __restrict__ th,
                            __nv_bfloat16* __restrict__ tl,
                            int R, int C)
{
    __shared__ float t[32][33];
    const int bx = blockIdx.x * 32;
    const int by = blockIdx.y * 32;
    const int tx = threadIdx.x, ty = threadIdx.y;
#pragma unroll
    for (int j = 0; j < 32; j += 8)
        t[ty + j][tx] = x[(size_t)(by + ty + j) * C + bx + tx];
    __syncthreads();
#pragma unroll
    for (int j = 0; j < 32; j += 8) {
        float v = t[tx][ty + j];
        __nv_bfloat16 hh = __float2bfloat16(v);
        float lo = v - __bfloat162float(hh);
        size_t o = (size_t)(bx + ty + j) * R + by + tx;
        th[o] = hh;
        tl[o] = __float2bfloat16(lo);
    }
}

/* ---------------- inv_freq table (fp64 pow once) -------------------- */
__global__ void init_freq()
{
    int d = threadIdx.x;
    g_invfreq[d] = (float)(1.0 / pow(1000000.0, (double)d / (double)(D / 2)));
}

/* ---------------- RMSNorm + RoPE + bf16 split -----------------------
   blockIdx.y: 0..NH-1 q heads | NH..NH+NKV-1 k heads | then v heads. */
__global__ __launch_bounds__(128) void normrope_kernel(const int* __restrict__ positions,
                                                       const float* __restrict__ q_norm_w,
                                                       const float* __restrict__ k_norm_w,
                                                       int T)
{
    const int t = blockIdx.x;
    const int h = blockIdx.y;
    const int d = threadIdx.x;

    if (h >= NH + NKV) {                       /* V: split only */
        int hv = h - NH - NKV;
        float v = g_qkv[(size_t)t * QKV_N + (NH + NKV) * D + hv * D + d];
        __nv_bfloat16 hh = __float2bfloat16(v);
        size_t o = ((size_t)t * NKV + hv) * D + d;
        g_vh[o] = hh;
        g_vl[o] = __float2bfloat16(v - __bfloat162float(hh));
        return;
    }

    const float* src;
    const float* w;
    __nv_bfloat16 *dsth, *dstl;
    float sc;
    if (h < NH) {
        src = g_qkv + (size_t)t * QKV_N + h * D;
        w = q_norm_w;
        dsth = g_qh + ((size_t)t * NH + h) * D;
        dstl = g_ql + ((size_t)t * NH + h) * D;
        sc = 0.08838834764831845f;             /* 1/sqrt(128) */
    } else {
        int hk = h - NH;
        src = g_qkv + (size_t)t * QKV_N + NH * D + hk * D;
        w = k_norm_w;
        dsth = g_kh + ((size_t)t * NKV + hk) * D;
        dstl = g_kl + ((size_t)t * NKV + hk) * D;
        sc = 1.0f;
    }

    float x = src[d];
    float ss = x * x;
#pragma unroll
    for (int o = 16; o > 0; o >>= 1) ss += __shfl_xor_sync(0xFFFFFFFFu, ss, o);

    __shared__ float red[4];
    __shared__ float s[D];
    if ((d & 31) == 0) red[d >> 5] = ss;
    __syncthreads();
    float var = (red[0] + red[1] + red[2] + red[3]) * (1.0f / (float)D);
    float nx = x * rsqrtf(var + 1e-6f) * w[d];
    s[d] = nx;
    __syncthreads();

    if (d < D / 2) {
        float p = (float)positions[t];
        float ang = p * g_invfreq[d];
        float c = cosf(ang);
        float si = sinf(ang);
        float x1 = s[d];
        float x2 = s[d + D / 2];
        float y1 = (x1 * c - x2 * si) * sc;
        float y2 = (x2 * c + x1 * si) * sc;
        __nv_bfloat16 h1 = __float2bfloat16(y1);
        __nv_bfloat16 h2 = __float2bfloat16(y2);
        dsth[d]         = h1;
        dsth[d + D / 2] = h2;
        dstl[d]         = __float2bfloat16(y1 - __bfloat162float(h1));
        dstl[d + D / 2] = __float2bfloat16(y2 - __bfloat162float(h2));
    }
}

/* ---------------- causal flash attention (mma.sync, split bf16) -----
   Block: 4 warps, 64 q-rows (16/warp); key tiles of 64; D = 128.
   smem tiles [rows][128 bf16] = 256B rows, seg swizzle s^(r&7).
   S = Qh Kh^T + Qh Kl^T + Ql Kh^T;  O += Ph V.. (same 3-way split).  */
#define A_QH 0
#define A_QL 16384
#define A_KH 32768
#define A_KL 49152
#define A_VH 65536
#define A_VL 81920
#define ASM_TOTAL 98304

__global__ __launch_bounds__(128) void attn_kernel(int T_)
{
    extern __shared__ char asmem[];
    const uint32_t sb = smem_u32(asmem);

    const int h   = blockIdx.y;
    const int hk  = h >> 1;
    const int bi  = gridDim.x - 1 - blockIdx.x;    /* heavy first */
    const int m0  = bi * 64;
    const int tid = threadIdx.x;
    const int wid = tid >> 5;
    const int lid = tid & 31;
    const int wrow = wid * 16;

    /* load Q tiles (qh, ql) */
#pragma unroll
    for (int it = 0; it < 8; it++) {
        int idx = tid + it * 128;                  /* 0..1023 */
        int r = idx >> 4, s = idx & 15;
        uint32_t off = (uint32_t)(r * 256 + ((s ^ (r & 7)) << 4));
        size_t g = ((size_t)(m0 + r) * NH + h) * D + s * 8;
        *(uint4*)(asmem + A_QH + off) = *(const uint4*)(g_qh + g);
        *(uint4*)(asmem + A_QL + off) = *(const uint4*)(g_ql + g);
    }

    float o[16][4];
#pragma unroll
    for (int i = 0; i < 16; i++)
#pragma unroll
        for (int u = 0; u < 4; u++) o[i][u] = 0.f;

    const int r0g = m0 + wrow + (lid >> 2);
    const int r1g = r0g + 8;
    float mrow0 = -1e30f, mrow1 = -1e30f;
    float lsum0 = 0.f, lsum1 = 0.f;

    const int ntiles = bi + 1;
    for (int kt = 0; kt < ntiles; kt++) {
        const int k0 = kt * 64;
        __syncthreads();
        /* load K/V split tiles */
#pragma unroll
        for (int it = 0; it < 8; it++) {
            int idx = tid + it * 128;
            int r = idx >> 4, s = idx & 15;
            uint32_t off = (uint32_t)(r * 256 + ((s ^ (r & 7)) << 4));
            size_t g = ((size_t)(k0 + r) * NKV + hk) * D + s * 8;
            *(uint4*)(asmem + A_KH + off) = *(const uint4*)(g_kh + g);
            *(uint4*)(asmem + A_KL + off) = *(const uint4*)(g_kl + g);
            *(uint4*)(asmem + A_VH + off) = *(const uint4*)(g_vh + g);
            *(uint4*)(asmem + A_VL + off) = *(const uint4*)(g_vl + g);
        }
        __syncthreads();

        /* ---- S = Q K^T ---- */
        float sa[8][4];
#pragma unroll
        for (int nb = 0; nb < 8; nb++)
#pragma unroll
            for (int u = 0; u < 4; u++) sa[nb][u] = 0.f;

#pragma unroll
        for (int kb = 0; kb < 8; kb++) {
            int qr = wrow + (lid & 15);
            int qs = 2 * kb + (lid >> 4);
            uint32_t qoff = (uint32_t)(qr * 256 + ((qs ^ (qr & 7)) << 4));
            uint32_t qh0, qh1, qh2, qh3, ql0, ql1, ql2, ql3;
            LDSM_X4(qh0, qh1, qh2, qh3, sb + A_QH + qoff);
            LDSM_X4(ql0, ql1, ql2, ql3, sb + A_QL + qoff);
#pragma unroll
            for (int nb16 = 0; nb16 < 4; nb16++) {
                int kr = nb16 * 16 + (lid & 15);
                int ks = 2 * kb + (lid >> 4);
                uint32_t koff = (uint32_t)(kr * 256 + ((ks ^ (kr & 7)) << 4));
                uint32_t t0, t1, t2, t3, u0, u1, u2, u3;
                LDSM_X4(t0, t1, t2, t3, sb + A_KH + koff);
                LDSM_X4(u0, u1, u2, u3, sb + A_KL + koff);
                MMA16816(sa[2 * nb16 + 0], qh0, qh1, qh2, qh3, t0, t2);
                MMA16816(sa[2 * nb16 + 1], qh0, qh1, qh2, qh3, t1, t3);
                MMA16816(sa[2 * nb16 + 0], qh0, qh1, qh2, qh3, u0, u2);
                MMA16816(sa[2 * nb16 + 1], qh0, qh1, qh2, qh3, u1, u3);
                MMA16816(sa[2 * nb16 + 0], ql0, ql1, ql2, ql3, t0, t2);
                MMA16816(sa[2 * nb16 + 1], ql0, ql1, ql2, ql3, t1, t3);
            }
        }

        /* ---- mask + online softmax ---- */
        float mx0 = mrow0, mx1 = mrow1;
#pragma unroll
        for (int nb = 0; nb < 8; nb++) {
            int col = k0 + nb * 8 + 2 * (lid & 3);
            if (col > r0g)     sa[nb][0] = -1e30f;
            if (col + 1 > r0g) sa[nb][1] = -1e30f;
            if (col > r1g)     sa[nb][2] = -1e30f;
            if (col + 1 > r1g) sa[nb][3] = -1e30f;
            mx0 = fmaxf(mx0, fmaxf(sa[nb][0], sa[nb][1]));
            mx1 = fmaxf(mx1, fmaxf(sa[nb][2], sa[nb][3]));
        }
        mx0 = fmaxf(mx0, __shfl_xor_sync(0xFFFFFFFFu, mx0, 1));
        mx0 = fmaxf(mx0, __shfl_xor_sync(0xFFFFFFFFu, mx0, 2));
        mx1 = fmaxf(mx1, __shfl_xor_sync(0xFFFFFFFFu, mx1, 1));
        mx1 = fmaxf(mx1, __shfl_xor_sync(0xFFFFFFFFu, mx1, 2));

        float corr0 = __expf(mrow0 - mx0);
        float corr1 = __expf(mrow1 - mx1);
        mrow0 = mx0; mrow1 = mx1;

        float ps0 = 0.f, ps1 = 0.f;
#pragma unroll
        for (int nb = 0; nb < 8; nb++) {
            sa[nb][0] = __expf(sa[nb][0] - mx0);
            sa[nb][1] = __expf(sa[nb][1] - mx0);
            sa[nb][2] = __expf(sa[nb][2] - mx1);
            sa[nb][3] = __expf(sa[nb][3] - mx1);
            ps0 += sa[nb][0] + sa[nb][1];
            ps1 += sa[nb][2] + sa[nb][3];
        }
        ps0 += __shfl_xor_sync(0xFFFFFFFFu, ps0, 1);
        ps0 += __shfl_xor_sync(0xFFFFFFFFu, ps0, 2);
        ps1 += __shfl_xor_sync(0xFFFFFFFFu, ps1, 1);
        ps1 += __shfl_xor_sync(0xFFFFFFFFu, ps1, 2);
        lsum0 = lsum0 * corr0 + ps0;
        lsum1 = lsum1 * corr1 + ps1;

        /* rescale O */
#pragma unroll
        for (int i = 0; i < 16; i++) {
            o[i][0] *= corr0; o[i][1] *= corr0;
            o[i][2] *= corr1; o[i][3] *= corr1;
        }

        /* ---- O += P V ---- */
#pragma unroll
        for (int jb = 0; jb < 4; jb++) {
            /* P fragments (Ph + residual Pl) from acc layout */
            float p00 = sa[2 * jb][0],     p01 = sa[2 * jb][1];
            float p02 = sa[2 * jb][2],     p03 = sa[2 * jb][3];
            float p10 = sa[2 * jb + 1][0], p11 = sa[2 * jb + 1][1];
            float p12 = sa[2 * jb + 1][2], p13 = sa[2 * jb + 1][3];
            uint32_t ph0 = packbf(p00, p01), ph1 = packbf(p02, p03);
            uint32_t ph2 = packbf(p10, p11), ph3 = packbf(p12, p13);
            uint32_t pl0 = packbf(p00 - __bfloat162float(__float2bfloat16(p00)),
                                  p01 - __bfloat162float(__float2bfloat16(p01)));
            uint32_t pl1 = packbf(p02 - __bfloat162float(__float2bfloat16(p02)),
                                  p03 - __bfloat162float(__float2bfloat16(p03)));
            uint32_t pl2 = packbf(p10 - __bfloat162float(__float2bfloat16(p10)),
                                  p11 - __bfloat162float(__float2bfloat16(p11)));
            uint32_t pl3 = packbf(p12 - __bfloat162float(__float2bfloat16(p12)),
                                  p13 - __bfloat162float(__float2bfloat16(p13)));

            int m = lid >> 3;
            int vr = jb * 16 + (lid & 7) + 8 * (m & 1);
#pragma unroll
            for (int dn = 0; dn < 8; dn++) {
                int vs = 2 * dn + (m >> 1);
                uint32_t voff = (uint32_t)(vr * 256 + ((vs ^ (vr & 7)) << 4));
                uint32_t v0, v1, v2, v3, w0, w1, w2, w3;
                LDSM_X4_T(v0, v1, v2, v3, sb + A_VH + voff);
                LDSM_X4_T(w0, w1, w2, w3, sb + A_VL + voff);
                MMA16816(o[2 * dn + 0], ph0, ph1, ph2, ph3, v0, v1);
                MMA16816(o[2 * dn + 1], ph0, ph1, ph2, ph3, v2, v3);
                MMA16816(o[2 * dn + 0], ph0, ph1, ph2, ph3, w0, w1);
                MMA16816(o[2 * dn + 1], ph0, ph1, ph2, ph3, w2, w3);
                MMA16816(o[2 * dn + 0], pl0, pl1, pl2, pl3, v0, v1);
                MMA16816(o[2 * dn + 1], pl0, pl1, pl2, pl3, v2, v3);
            }
        }
    }

    /* epilogue: normalize, split to bf16 h/l, store */
    const float inv0 = 1.f / lsum0;
    const float inv1 = 1.f / lsum1;
#pragma unroll
    for (int dn = 0; dn < 16; dn++) {
        int col = dn * 8 + 2 * (lid & 3);
        float a0 = o[dn][0] * inv0, a1 = o[dn][1] * inv0;
        float b0 = o[dn][2] * inv1, b1 = o[dn][3] * inv1;
        __nv_bfloat16 ha0 = __float2bfloat16(a0), ha1 = __float2bfloat16(a1);
        __nv_bfloat16 hb0 = __float2bfloat16(b0), hb1 = __float2bfloat16(b1);
        uint32_t hA = packbf(a0, a1);
        uint32_t lA = packbf(a0 - __bfloat162float(ha0), a1 - __bfloat162float(ha1));
        uint32_t hB = packbf(b0, b1);
        uint32_t lB = packbf(b0 - __bfloat162float(hb0), b1 - __bfloat162float(hb1));
        size_t iA = (size_t)r0g * (NH * D) + h * D + col;
        size_t iB = (size_t)r1g * (NH * D) + h * D + col;
        *(uint32_t*)(g_oth + iA) = hA;
        *(uint32_t*)(g_otl + iA) = lA;
        *(uint32_t*)(g_oth + iB) = hB;
        *(uint32_t*)(g_otl + iB) = lB;
    }
}

/* ---------------- launch -------------------------------------------- */
extern "C" void kernel_launch(void* const* d_in, const int* in_sizes, int n_in,
                              void* d_out, int out_size)
{
    const int*   positions = (const int*)d_in[0];
    const float* hidden    = (const float*)d_in[1];
    const float* w_qkv     = (const float*)d_in[2];
    const float* q_norm_w  = (const float*)d_in[3];
    const float* k_norm_w  = (const float*)d_in[4];
    const float* w_o       = (const float*)d_in[5];
    float*       out       = (float*)d_out;
    const int    T         = in_sizes[0];   /* 2048 */

    __nv_bfloat16 *ah, *al, *wqh, *wql, *oh, *ol, *woh, *wol;
    cudaGetSymbolAddress((void**)&ah,  g_ah);
    cudaGetSymbolAddress((void**)&al,  g_al);
    cudaGetSymbolAddress((void**)&wqh, g_wqt_h);
    cudaGetSymbolAddress((void**)&wql, g_wqt_l);
    cudaGetSymbolAddress((void**)&oh,  g_oth);
    cudaGetSymbolAddress((void**)&ol,  g_otl);
    cudaGetSymbolAddress((void**)&woh, g_wot_h);
    cudaGetSymbolAddress((void**)&wol, g_wot_l);

    cudaFuncSetAttribute(tc_gemm, cudaFuncAttributeMaxDynamicSharedMemorySize, GSM_TOTAL);
    cudaFuncSetAttribute(attn_kernel, cudaFuncAttributeMaxDynamicSharedMemorySize, ASM_TOTAL);

    /* 0) inv_freq table + input splits */
    init_freq<<<1, D / 2>>>();
    cvt_split<<<(T * HID) / 1024, 256>>>(hidden, ah, al, T * HID);
    cvt_split_t<<<dim3(QKV_N / 32, HID / 32), dim3(32, 8)>>>(w_qkv, wqh, wql, HID, QKV_N);

    /* 1) QKV projection */
    {
        float* cq;
        cudaGetSymbolAddress((void**)&cq, g_qkv);
        dim3 g(QKV_N / 128, T / 128);
        tc_gemm<<<g, 256, GSM_TOTAL>>>(ah, al, wqh, wql, cq, T, QKV_N, HID);
    }

    /* 2) RMSNorm + RoPE + bf16 splits for q/k/v */
    dim3 g2(T, NH + 2 * NKV);
    normrope_kernel<<<g2, 128>>>(positions, q_norm_w, k_norm_w, T);

    /* 3) causal GQA flash attention (tensor cores, writes split output) */
    dim3 g3(T / 64, NH);
    attn_kernel<<<g3, 128, ASM_TOTAL>>>(T);

    /* 4) output projection */
    cvt_split_t<<<dim3(HID / 32, (NH * D) / 32), dim3(32, 8)>>>(w_o, woh, wol, NH * D, HID);
    {
        dim3 g(HID / 128, T / 128);
        tc_gemm<<<g, 256, GSM_TOTAL>>>(oh, ol, woh, wol, out, T, HID, HID);
    }
}

// round 9
// speedup vs baseline: 4.6668x; 1.9653x over previous
#include <cuda_runtime.h>
#include <cuda_bf16.h>
#include <stdint.h>
#include <math.h>

#define NH   16
#define NKV  8
#define D    128
#define HID  2048
#define QKV_N ((NH + 2 * NKV) * D)   /* 4096 */
#define MAXT 2048

/* ---------------- scratch (no allocations allowed) ---------------- */
__device__ float g_qkv [(size_t)MAXT * QKV_N];
__device__ float g_invfreq[D / 2];

/* split-bf16 operands */
__device__ __nv_bfloat16 g_ah  [(size_t)MAXT * HID];
__device__ __nv_bfloat16 g_al  [(size_t)MAXT * HID];
__device__ __nv_bfloat16 g_wqt_h[(size_t)QKV_N * HID];
__device__ __nv_bfloat16 g_wqt_l[(size_t)QKV_N * HID];
__device__ __nv_bfloat16 g_wot_h[(size_t)HID * HID];
__device__ __nv_bfloat16 g_wot_l[(size_t)HID * HID];

/* attention operands / outputs (all compensated bf16 splits) */
__device__ __nv_bfloat16 g_qh[(size_t)MAXT * NH  * D];
__device__ __nv_bfloat16 g_ql[(size_t)MAXT * NH  * D];
__device__ __nv_bfloat16 g_kh[(size_t)MAXT * NKV * D];
__device__ __nv_bfloat16 g_kl[(size_t)MAXT * NKV * D];
__device__ __nv_bfloat16 g_vh[(size_t)MAXT * NKV * D];
__device__ __nv_bfloat16 g_vl[(size_t)MAXT * NKV * D];
__device__ __nv_bfloat16 g_oth[(size_t)MAXT * NH * D];
__device__ __nv_bfloat16 g_otl[(size_t)MAXT * NH * D];

/* ================= helpers ========================================= */
__device__ __forceinline__ uint32_t smem_u32(const void* p) {
    uint32_t a;
    asm("{ .reg .u64 t; cvta.to.shared.u64 t, %1; cvt.u32.u64 %0, t; }"
        : "=r"(a) : "l"(p));
    return a;
}

#define CP_ASYNC16(dst, src)                                                   \
    asm volatile("cp.async.cg.shared.global [%0], [%1], 16;"                   \
        :: "r"(dst), "l"(src))
#define CP_COMMIT() asm volatile("cp.async.commit_group;" ::: "memory")
#define CP_WAIT(n)  asm volatile("cp.async.wait_group %0;" :: "n"(n) : "memory")

#define LDSM_X4(r0, r1, r2, r3, addr)                                          \
    asm volatile("ldmatrix.sync.aligned.m8n8.x4.shared.b16 {%0,%1,%2,%3}, [%4];" \
        : "=r"(r0), "=r"(r1), "=r"(r2), "=r"(r3) : "r"(addr))

#define LDSM_X4_T(r0, r1, r2, r3, addr)                                        \
    asm volatile("ldmatrix.sync.aligned.m8n8.x4.trans.shared.b16 {%0,%1,%2,%3}, [%4];" \
        : "=r"(r0), "=r"(r1), "=r"(r2), "=r"(r3) : "r"(addr))

#define MMA16816(d, a0, a1, a2, a3, b0, b1)                                    \
    asm volatile("mma.sync.aligned.m16n8k16.row.col.f32.bf16.bf16.f32 "        \
        "{%0,%1,%2,%3}, {%4,%5,%6,%7}, {%8,%9}, {%0,%1,%2,%3};"                \
        : "+f"((d)[0]), "+f"((d)[1]), "+f"((d)[2]), "+f"((d)[3])               \
        : "r"(a0), "r"(a1), "r"(a2), "r"(a3), "r"(b0), "r"(b1))

__device__ __forceinline__ uint32_t packbf(float lo, float hi) {
    uint32_t r;
    asm("cvt.rn.bf16x2.f32 %0, %1, %2;" : "=r"(r) : "f"(hi), "f"(lo));
    return r;
}

/* ================= split-bf16 tensor GEMM (cp.async pipelined) ===== */
#define KC      64
#define TILE_B  (128 * 128)
#define STAGE_B (4 * TILE_B)
#define GSM_TOTAL (2 * STAGE_B)

__device__ __forceinline__ void load_tiles_async(uint32_t sbase, int st,
    const __nv_bfloat16* Ah, const __nv_bfloat16* Al,
    const __nv_bfloat16* Bh, const __nv_bfloat16* Bl,
    int m0, int n0, int K, int k0)
{
    uint32_t base = sbase + st * STAGE_B;
    const int tid = threadIdx.x;
    const __nv_bfloat16* srcs[4] = {Ah, Al, Bh, Bl};
#pragma unroll
    for (int it = 0; it < 16; it++) {
        int gidx = tid + it * 256;
        int tile = gidx >> 10;
        int r    = (gidx >> 3) & 127;
        int s    = gidx & 7;
        int row0 = (tile < 2) ? m0 : n0;
        const __nv_bfloat16* src = srcs[tile] + (size_t)(row0 + r) * K + k0 + s * 8;
        uint32_t dst = base + tile * TILE_B + r * 128 + ((s ^ (r & 7)) << 4);
        CP_ASYNC16(dst, src);
    }
}

__global__ __launch_bounds__(256, 1) void tc_gemm(
    const __nv_bfloat16* __restrict__ Ah, const __nv_bfloat16* __restrict__ Al,
    const __nv_bfloat16* __restrict__ Bh, const __nv_bfloat16* __restrict__ Bl,
    float* __restrict__ C, int M, int N, int K)
{
    extern __shared__ char smem[];
    const int tid = threadIdx.x;
    const int wid = tid >> 5;
    const int lid = tid & 31;
    const int mw  = wid & 1;
    const int nw  = wid >> 1;
    const int m0  = blockIdx.y * 128;
    const int n0  = blockIdx.x * 128;

    const uint32_t sb = smem_u32(smem);

    float acc[4][4][4];
#pragma unroll
    for (int i = 0; i < 4; i++)
#pragma unroll
        for (int j = 0; j < 4; j++)
#pragma unroll
            for (int u = 0; u < 4; u++) acc[i][j][u] = 0.f;

    load_tiles_async(sb, 0, Ah, Al, Bh, Bl, m0, n0, K, 0);
    CP_COMMIT();

    const int nch = K / KC;
    for (int c = 0; c < nch; c++) {
        const int st = c & 1;
        if (c + 1 < nch) {
            load_tiles_async(sb, st ^ 1, Ah, Al, Bh, Bl, m0, n0, K, (c + 1) * KC);
            CP_COMMIT();
            CP_WAIT(1);            /* stage c complete; c+1 in flight */
        } else {
            CP_WAIT(0);
        }
        __syncthreads();

        const uint32_t tAh = sb + st * STAGE_B + 0 * TILE_B;
        const uint32_t tAl = sb + st * STAGE_B + 1 * TILE_B;
        const uint32_t tBh = sb + st * STAGE_B + 2 * TILE_B;
        const uint32_t tBl = sb + st * STAGE_B + 3 * TILE_B;

#pragma unroll
        for (int kb = 0; kb < KC / 16; kb++) {
            uint32_t ah[4][4], al[4][4];
#pragma unroll
            for (int mf = 0; mf < 4; mf++) {
                int r = mw * 64 + mf * 16 + (lid & 15);
                int s = 2 * kb + (lid >> 4);
                uint32_t off = (uint32_t)(r * 128 + ((s ^ (r & 7)) << 4));
                LDSM_X4(ah[mf][0], ah[mf][1], ah[mf][2], ah[mf][3], tAh + off);
                LDSM_X4(al[mf][0], al[mf][1], al[mf][2], al[mf][3], tAl + off);
            }
            uint32_t bh[4][2], bl[4][2];
#pragma unroll
            for (int nb = 0; nb < 2; nb++) {
                int r = nw * 32 + nb * 16 + (lid & 15);
                int s = 2 * kb + (lid >> 4);
                uint32_t off = (uint32_t)(r * 128 + ((s ^ (r & 7)) << 4));
                uint32_t r0, r1, r2, r3;
                LDSM_X4(r0, r1, r2, r3, tBh + off);
                bh[2 * nb + 0][0] = r0; bh[2 * nb + 0][1] = r2;
                bh[2 * nb + 1][0] = r1; bh[2 * nb + 1][1] = r3;
                LDSM_X4(r0, r1, r2, r3, tBl + off);
                bl[2 * nb + 0][0] = r0; bl[2 * nb + 0][1] = r2;
                bl[2 * nb + 1][0] = r1; bl[2 * nb + 1][1] = r3;
            }
#pragma unroll
            for (int mf = 0; mf < 4; mf++)
#pragma unroll
                for (int j = 0; j < 4; j++) {
                    MMA16816(acc[mf][j], ah[mf][0], ah[mf][1], ah[mf][2], ah[mf][3],
                             bh[j][0], bh[j][1]);
                    MMA16816(acc[mf][j], ah[mf][0], ah[mf][1], ah[mf][2], ah[mf][3],
                             bl[j][0], bl[j][1]);
                    MMA16816(acc[mf][j], al[mf][0], al[mf][1], al[mf][2], al[mf][3],
                             bh[j][0], bh[j][1]);
                }
        }
        __syncthreads();
    }

#pragma unroll
    for (int mf = 0; mf < 4; mf++) {
        int rbase = m0 + mw * 64 + mf * 16 + (lid >> 2);
#pragma unroll
        for (int j = 0; j < 4; j++) {
            int col = n0 + nw * 32 + j * 8 + 2 * (lid & 3);
            *(float2*)&C[(size_t)rbase * N + col] =
                make_float2(acc[mf][j][0], acc[mf][j][1]);
            *(float2*)&C[(size_t)(rbase + 8) * N + col] =
                make_float2(acc[mf][j][2], acc[mf][j][3]);
        }
    }
}

/* ================= split conversion kernels ======================== */
__global__ __launch_bounds__(256) void cvt_split(const float* __restrict__ x,
                                                 __nv_bfloat16* __restrict__ h,
                                                 __nv_bfloat16* __restrict__ l,
                                                 int n)
{
    int i = (blockIdx.x * 256 + threadIdx.x) * 4;
    if (i >= n) return;
    float4 v = *(const float4*)(x + i);
    float vv[4] = {v.x, v.y, v.z, v.w};
    __nv_bfloat16 hh[4], ll[4];
#pragma unroll
    for (int j = 0; j < 4; j++) {
        hh[j] = __float2bfloat16(vv[j]);
        ll[j] = __float2bfloat16(vv[j] - __bfloat162float(hh[j]));
    }
    *(uint2*)(h + i) = *(uint2*)hh;
    *(uint2*)(l + i) = *(uint2*)ll;
}

__global__ void cvt_split_t(const float* __restrict__ x,
                            __nv_bfloat16* __restrict__ th,
                            __nv_bfloat16* __restrict__ tl,
                            int R, int C)
{
    __shared__ float t[32][33];
    const int bx = blockIdx.x * 32;
    const int by = blockIdx.y * 32;
    const int tx = threadIdx.x, ty = threadIdx.y;
#pragma unroll
    for (int j = 0; j < 32; j += 8)
        t[ty + j][tx] = x[(size_t)(by + ty + j) * C + bx + tx];
    __syncthreads();
#pragma unroll
    for (int j = 0; j < 32; j += 8) {
        float v = t[tx][ty + j];
        __nv_bfloat16 hh = __float2bfloat16(v);
        float lo = v - __bfloat162float(hh);
        size_t o = (size_t)(bx + ty + j) * R + by + tx;
        th[o] = hh;
        tl[o] = __float2bfloat16(lo);
    }
}

/* ---------------- inv_freq table (fp64 pow once) -------------------- */
__global__ void init_freq()
{
    int d = threadIdx.x;
    g_invfreq[d] = (float)(1.0 / pow(1000000.0, (double)d / (double)(D / 2)));
}

/* ---------------- RMSNorm + RoPE + bf16 split ----------------------- */
__global__ __launch_bounds__(128) void normrope_kernel(const int* __restrict__ positions,
                                                       const float* __restrict__ q_norm_w,
                                                       const float* __restrict__ k_norm_w,
                                                       int T)
{
    const int t = blockIdx.x;
    const int h = blockIdx.y;
    const int d = threadIdx.x;

    if (h >= NH + NKV) {                       /* V: split only */
        int hv = h - NH - NKV;
        float v = g_qkv[(size_t)t * QKV_N + (NH + NKV) * D + hv * D + d];
        __nv_bfloat16 hh = __float2bfloat16(v);
        size_t o = ((size_t)t * NKV + hv) * D + d;
        g_vh[o] = hh;
        g_vl[o] = __float2bfloat16(v - __bfloat162float(hh));
        return;
    }

    const float* src;
    const float* w;
    __nv_bfloat16 *dsth, *dstl;
    float sc;
    if (h < NH) {
        src = g_qkv + (size_t)t * QKV_N + h * D;
        w = q_norm_w;
        dsth = g_qh + ((size_t)t * NH + h) * D;
        dstl = g_ql + ((size_t)t * NH + h) * D;
        sc = 0.08838834764831845f;
    } else {
        int hk = h - NH;
        src = g_qkv + (size_t)t * QKV_N + NH * D + hk * D;
        w = k_norm_w;
        dsth = g_kh + ((size_t)t * NKV + hk) * D;
        dstl = g_kl + ((size_t)t * NKV + hk) * D;
        sc = 1.0f;
    }

    float x = src[d];
    float ss = x * x;
#pragma unroll
    for (int o = 16; o > 0; o >>= 1) ss += __shfl_xor_sync(0xFFFFFFFFu, ss, o);

    __shared__ float red[4];
    __shared__ float s[D];
    if ((d & 31) == 0) red[d >> 5] = ss;
    __syncthreads();
    float var = (red[0] + red[1] + red[2] + red[3]) * (1.0f / (float)D);
    float nx = x * rsqrtf(var + 1e-6f) * w[d];
    s[d] = nx;
    __syncthreads();

    if (d < D / 2) {
        float p = (float)positions[t];
        float ang = p * g_invfreq[d];
        float c = cosf(ang);
        float si = sinf(ang);
        float x1 = s[d];
        float x2 = s[d + D / 2];
        float y1 = (x1 * c - x2 * si) * sc;
        float y2 = (x2 * c + x1 * si) * sc;
        __nv_bfloat16 h1 = __float2bfloat16(y1);
        __nv_bfloat16 h2 = __float2bfloat16(y2);
        dsth[d]         = h1;
        dsth[d + D / 2] = h2;
        dstl[d]         = __float2bfloat16(y1 - __bfloat162float(h1));
        dstl[d + D / 2] = __float2bfloat16(y2 - __bfloat162float(h2));
    }
}

/* ---------------- causal flash attention (mma.sync, split bf16) ----- */
#define A_QH 0
#define A_QL 16384
#define A_KH 32768
#define A_KL 49152
#define A_VH 65536
#define A_VL 81920
#define ASM_TOTAL 98304

__global__ __launch_bounds__(128) void attn_kernel(int T_)
{
    extern __shared__ char asmem[];
    const uint32_t sb = smem_u32(asmem);

    const int h   = blockIdx.y;
    const int hk  = h >> 1;
    const int bi  = gridDim.x - 1 - blockIdx.x;
    const int m0  = bi * 64;
    const int tid = threadIdx.x;
    const int wid = tid >> 5;
    const int lid = tid & 31;
    const int wrow = wid * 16;

    /* load Q tiles (qh, ql) via cp.async */
#pragma unroll
    for (int it = 0; it < 8; it++) {
        int idx = tid + it * 128;
        int r = idx >> 4, s = idx & 15;
        uint32_t off = (uint32_t)(r * 256 + ((s ^ (r & 7)) << 4));
        size_t g = ((size_t)(m0 + r) * NH + h) * D + s * 8;
        CP_ASYNC16(sb + A_QH + off, g_qh + g);
        CP_ASYNC16(sb + A_QL + off, g_ql + g);
    }
    CP_COMMIT();

    float o[16][4];
#pragma unroll
    for (int i = 0; i < 16; i++)
#pragma unroll
        for (int u = 0; u < 4; u++) o[i][u] = 0.f;

    const int r0g = m0 + wrow + (lid >> 2);
    const int r1g = r0g + 8;
    float mrow0 = -1e30f, mrow1 = -1e30f;
    float lsum0 = 0.f, lsum1 = 0.f;

    const int ntiles = bi + 1;
    for (int kt = 0; kt < ntiles; kt++) {
        const int k0 = kt * 64;
        __syncthreads();
        /* K/V split tiles via cp.async */
#pragma unroll
        for (int it = 0; it < 8; it++) {
            int idx = tid + it * 128;
            int r = idx >> 4, s = idx & 15;
            uint32_t off = (uint32_t)(r * 256 + ((s ^ (r & 7)) << 4));
            size_t g = ((size_t)(k0 + r) * NKV + hk) * D + s * 8;
            CP_ASYNC16(sb + A_KH + off, g_kh + g);
            CP_ASYNC16(sb + A_KL + off, g_kl + g);
            CP_ASYNC16(sb + A_VH + off, g_vh + g);
            CP_ASYNC16(sb + A_VL + off, g_vl + g);
        }
        CP_COMMIT();
        CP_WAIT(0);
        __syncthreads();

        /* ---- S = Q K^T ---- */
        float sa[8][4];
#pragma unroll
        for (int nb = 0; nb < 8; nb++)
#pragma unroll
            for (int u = 0; u < 4; u++) sa[nb][u] = 0.f;

#pragma unroll
        for (int kb = 0; kb < 8; kb++) {
            int qr = wrow + (lid & 15);
            int qs = 2 * kb + (lid >> 4);
            uint32_t qoff = (uint32_t)(qr * 256 + ((qs ^ (qr & 7)) << 4));
            uint32_t qh0, qh1, qh2, qh3, ql0, ql1, ql2, ql3;
            LDSM_X4(qh0, qh1, qh2, qh3, sb + A_QH + qoff);
            LDSM_X4(ql0, ql1, ql2, ql3, sb + A_QL + qoff);
#pragma unroll
            for (int nb16 = 0; nb16 < 4; nb16++) {
                int kr = nb16 * 16 + (lid & 15);
                int ks = 2 * kb + (lid >> 4);
                uint32_t koff = (uint32_t)(kr * 256 + ((ks ^ (kr & 7)) << 4));
                uint32_t t0, t1, t2, t3, u0, u1, u2, u3;
                LDSM_X4(t0, t1, t2, t3, sb + A_KH + koff);
                LDSM_X4(u0, u1, u2, u3, sb + A_KL + koff);
                MMA16816(sa[2 * nb16 + 0], qh0, qh1, qh2, qh3, t0, t2);
                MMA16816(sa[2 * nb16 + 1], qh0, qh1, qh2, qh3, t1, t3);
                MMA16816(sa[2 * nb16 + 0], qh0, qh1, qh2, qh3, u0, u2);
                MMA16816(sa[2 * nb16 + 1], qh0, qh1, qh2, qh3, u1, u3);
                MMA16816(sa[2 * nb16 + 0], ql0, ql1, ql2, ql3, t0, t2);
                MMA16816(sa[2 * nb16 + 1], ql0, ql1, ql2, ql3, t1, t3);
            }
        }

        /* ---- mask + online softmax ---- */
        float mx0 = mrow0, mx1 = mrow1;
#pragma unroll
        for (int nb = 0; nb < 8; nb++) {
            int col = k0 + nb * 8 + 2 * (lid & 3);
            if (col > r0g)     sa[nb][0] = -1e30f;
            if (col + 1 > r0g) sa[nb][1] = -1e30f;
            if (col > r1g)     sa[nb][2] = -1e30f;
            if (col + 1 > r1g) sa[nb][3] = -1e30f;
            mx0 = fmaxf(mx0, fmaxf(sa[nb][0], sa[nb][1]));
            mx1 = fmaxf(mx1, fmaxf(sa[nb][2], sa[nb][3]));
        }
        mx0 = fmaxf(mx0, __shfl_xor_sync(0xFFFFFFFFu, mx0, 1));
        mx0 = fmaxf(mx0, __shfl_xor_sync(0xFFFFFFFFu, mx0, 2));
        mx1 = fmaxf(mx1, __shfl_xor_sync(0xFFFFFFFFu, mx1, 1));
        mx1 = fmaxf(mx1, __shfl_xor_sync(0xFFFFFFFFu, mx1, 2));

        float corr0 = __expf(mrow0 - mx0);
        float corr1 = __expf(mrow1 - mx1);
        mrow0 = mx0; mrow1 = mx1;

        float ps0 = 0.f, ps1 = 0.f;
#pragma unroll
        for (int nb = 0; nb < 8; nb++) {
            sa[nb][0] = __expf(sa[nb][0] - mx0);
            sa[nb][1] = __expf(sa[nb][1] - mx0);
            sa[nb][2] = __expf(sa[nb][2] - mx1);
            sa[nb][3] = __expf(sa[nb][3] - mx1);
            ps0 += sa[nb][0] + sa[nb][1];
            ps1 += sa[nb][2] + sa[nb][3];
        }
        ps0 += __shfl_xor_sync(0xFFFFFFFFu, ps0, 1);
        ps0 += __shfl_xor_sync(0xFFFFFFFFu, ps0, 2);
        ps1 += __shfl_xor_sync(0xFFFFFFFFu, ps1, 1);
        ps1 += __shfl_xor_sync(0xFFFFFFFFu, ps1, 2);
        lsum0 = lsum0 * corr0 + ps0;
        lsum1 = lsum1 * corr1 + ps1;

#pragma unroll
        for (int i = 0; i < 16; i++) {
            o[i][0] *= corr0; o[i][1] *= corr0;
            o[i][2] *= corr1; o[i][3] *= corr1;
        }

        /* ---- O += P V ---- */
#pragma unroll
        for (int jb = 0; jb < 4; jb++) {
            float p00 = sa[2 * jb][0],     p01 = sa[2 * jb][1];
            float p02 = sa[2 * jb][2],     p03 = sa[2 * jb][3];
            float p10 = sa[2 * jb + 1][0], p11 = sa[2 * jb + 1][1];
            float p12 = sa[2 * jb + 1][2], p13 = sa[2 * jb + 1][3];
            uint32_t ph0 = packbf(p00, p01), ph1 = packbf(p02, p03);
            uint32_t ph2 = packbf(p10, p11), ph3 = packbf(p12, p13);
            uint32_t pl0 = packbf(p00 - __bfloat162float(__float2bfloat16(p00)),
                                  p01 - __bfloat162float(__float2bfloat16(p01)));
            uint32_t pl1 = packbf(p02 - __bfloat162float(__float2bfloat16(p02)),
                                  p03 - __bfloat162float(__float2bfloat16(p03)));
            uint32_t pl2 = packbf(p10 - __bfloat162float(__float2bfloat16(p10)),
                                  p11 - __bfloat162float(__float2bfloat16(p11)));
            uint32_t pl3 = packbf(p12 - __bfloat162float(__float2bfloat16(p12)),
                                  p13 - __bfloat162float(__float2bfloat16(p13)));

            int m = lid >> 3;
            int vr = jb * 16 + (lid & 7) + 8 * (m & 1);
#pragma unroll
            for (int dn = 0; dn < 8; dn++) {
                int vs = 2 * dn + (m >> 1);
                uint32_t voff = (uint32_t)(vr * 256 + ((vs ^ (vr & 7)) << 4));
                uint32_t v0, v1, v2, v3, w0, w1, w2, w3;
                LDSM_X4_T(v0, v1, v2, v3, sb + A_VH + voff);
                LDSM_X4_T(w0, w1, w2, w3, sb + A_VL + voff);
                MMA16816(o[2 * dn + 0], ph0, ph1, ph2, ph3, v0, v1);
                MMA16816(o[2 * dn + 1], ph0, ph1, ph2, ph3, v2, v3);
                MMA16816(o[2 * dn + 0], ph0, ph1, ph2, ph3, w0, w1);
                MMA16816(o[2 * dn + 1], ph0, ph1, ph2, ph3, w2, w3);
                MMA16816(o[2 * dn + 0], pl0, pl1, pl2, pl3, v0, v1);
                MMA16816(o[2 * dn + 1], pl0, pl1, pl2, pl3, v2, v3);
            }
        }
    }

    /* epilogue: normalize, split to bf16 h/l, store */
    const float inv0 = 1.f / lsum0;
    const float inv1 = 1.f / lsum1;
#pragma unroll
    for (int dn = 0; dn < 16; dn++) {
        int col = dn * 8 + 2 * (lid & 3);
        float a0 = o[dn][0] * inv0, a1 = o[dn][1] * inv0;
        float b0 = o[dn][2] * inv1, b1 = o[dn][3] * inv1;
        __nv_bfloat16 ha0 = __float2bfloat16(a0), ha1 = __float2bfloat16(a1);
        __nv_bfloat16 hb0 = __float2bfloat16(b0), hb1 = __float2bfloat16(b1);
        uint32_t hA = packbf(a0, a1);
        uint32_t lA = packbf(a0 - __bfloat162float(ha0), a1 - __bfloat162float(ha1));
        uint32_t hB = packbf(b0, b1);
        uint32_t lB = packbf(b0 - __bfloat162float(hb0), b1 - __bfloat162float(hb1));
        size_t iA = (size_t)r0g * (NH * D) + h * D + col;
        size_t iB = (size_t)r1g * (NH * D) + h * D + col;
        *(uint32_t*)(g_oth + iA) = hA;
        *(uint32_t*)(g_otl + iA) = lA;
        *(uint32_t*)(g_oth + iB) = hB;
        *(uint32_t*)(g_otl + iB) = lB;
    }
}

/* ---------------- launch -------------------------------------------- */
extern "C" void kernel_launch(void* const* d_in, const int* in_sizes, int n_in,
                              void* d_out, int out_size)
{
    const int*   positions = (const int*)d_in[0];
    const float* hidden    = (const float*)d_in[1];
    const float* w_qkv     = (const float*)d_in[2];
    const float* q_norm_w  = (const float*)d_in[3];
    const float* k_norm_w  = (const float*)d_in[4];
    const float* w_o       = (const float*)d_in[5];
    float*       out       = (float*)d_out;
    const int    T         = in_sizes[0];   /* 2048 */

    __nv_bfloat16 *ah, *al, *wqh, *wql, *oh, *ol, *woh, *wol;
    cudaGetSymbolAddress((void**)&ah,  g_ah);
    cudaGetSymbolAddress((void**)&al,  g_al);
    cudaGetSymbolAddress((void**)&wqh, g_wqt_h);
    cudaGetSymbolAddress((void**)&wql, g_wqt_l);
    cudaGetSymbolAddress((void**)&oh,  g_oth);
    cudaGetSymbolAddress((void**)&ol,  g_otl);
    cudaGetSymbolAddress((void**)&woh, g_wot_h);
    cudaGetSymbolAddress((void**)&wol, g_wot_l);

    cudaFuncSetAttribute(tc_gemm, cudaFuncAttributeMaxDynamicSharedMemorySize, GSM_TOTAL);
    cudaFuncSetAttribute(attn_kernel, cudaFuncAttributeMaxDynamicSharedMemorySize, ASM_TOTAL);

    /* 0) inv_freq table + input splits */
    init_freq<<<1, D / 2>>>();
    cvt_split<<<(T * HID) / 1024, 256>>>(hidden, ah, al, T * HID);
    cvt_split_t<<<dim3(QKV_N / 32, HID / 32), dim3(32, 8)>>>(w_qkv, wqh, wql, HID, QKV_N);

    /* 1) QKV projection */
    {
        float* cq;
        cudaGetSymbolAddress((void**)&cq, g_qkv);
        dim3 g(QKV_N / 128, T / 128);
        tc_gemm<<<g, 256, GSM_TOTAL>>>(ah, al, wqh, wql, cq, T, QKV_N, HID);
    }

    /* 2) RMSNorm + RoPE + bf16 splits for q/k/v */
    dim3 g2(T, NH + 2 * NKV);
    normrope_kernel<<<g2, 128>>>(positions, q_norm_w, k_norm_w, T);

    /* 3) causal GQA flash attention */
    dim3 g3(T / 64, NH);
    attn_kernel<<<g3, 128, ASM_TOTAL>>>(T);

    /* 4) output projection */
    cvt_split_t<<<dim3(HID / 32, (NH * D) / 32), dim3(32, 8)>>>(w_o, woh, wol, NH * D, HID);
    {
        dim3 g(HID / 128, T / 128);
        tc_gemm<<<g, 256, GSM_TOTAL>>>(oh, ol, woh, wol, out, T, HID, HID);
    }
}

// round 10
// speedup vs baseline: 4.9047x; 1.0510x over previous
#include <cuda_runtime.h>
#include <cuda_bf16.h>
#include <stdint.h>
#include <math.h>

#define NH   16
#define NKV  8
#define D    128
#define HID  2048
#define QKV_N ((NH + 2 * NKV) * D)   /* 4096 */
#define MAXT 2048

/* ---------------- scratch (no allocations allowed) ---------------- */
__device__ float g_qkv [(size_t)MAXT * QKV_N];
__device__ float g_invfreq[D / 2];

/* split-bf16 operands */
__device__ __nv_bfloat16 g_ah  [(size_t)MAXT * HID];
__device__ __nv_bfloat16 g_al  [(size_t)MAXT * HID];
__device__ __nv_bfloat16 g_wqt_h[(size_t)QKV_N * HID];
__device__ __nv_bfloat16 g_wqt_l[(size_t)QKV_N * HID];
__device__ __nv_bfloat16 g_wot_h[(size_t)HID * HID];
__device__ __nv_bfloat16 g_wot_l[(size_t)HID * HID];

/* attention operands / outputs (all compensated bf16 splits) */
__device__ __nv_bfloat16 g_qh[(size_t)MAXT * NH  * D];
__device__ __nv_bfloat16 g_ql[(size_t)MAXT * NH  * D];
__device__ __nv_bfloat16 g_kh[(size_t)MAXT * NKV * D];
__device__ __nv_bfloat16 g_kl[(size_t)MAXT * NKV * D];
__device__ __nv_bfloat16 g_vh[(size_t)MAXT * NKV * D];
__device__ __nv_bfloat16 g_vl[(size_t)MAXT * NKV * D];
__device__ __nv_bfloat16 g_oth[(size_t)MAXT * NH * D];
__device__ __nv_bfloat16 g_otl[(size_t)MAXT * NH * D];

/* ================= helpers ========================================= */
__device__ __forceinline__ uint32_t smem_u32(const void* p) {
    uint32_t a;
    asm("{ .reg .u64 t; cvta.to.shared.u64 t, %1; cvt.u32.u64 %0, t; }"
        : "=r"(a) : "l"(p));
    return a;
}

#define CP_ASYNC16(dst, src)                                                   \
    asm volatile("cp.async.cg.shared.global [%0], [%1], 16;"                   \
        :: "r"(dst), "l"(src))
#define CP_COMMIT() asm volatile("cp.async.commit_group;" ::: "memory")
#define CP_WAIT(n)  asm volatile("cp.async.wait_group %0;" :: "n"(n) : "memory")

#define LDSM_X4(r0, r1, r2, r3, addr)                                          \
    asm volatile("ldmatrix.sync.aligned.m8n8.x4.shared.b16 {%0,%1,%2,%3}, [%4];" \
        : "=r"(r0), "=r"(r1), "=r"(r2), "=r"(r3) : "r"(addr))

#define LDSM_X4_T(r0, r1, r2, r3, addr)                                        \
    asm volatile("ldmatrix.sync.aligned.m8n8.x4.trans.shared.b16 {%0,%1,%2,%3}, [%4];" \
        : "=r"(r0), "=r"(r1), "=r"(r2), "=r"(r3) : "r"(addr))

#define MMA16816(d, a0, a1, a2, a3, b0, b1)                                    \
    asm volatile("mma.sync.aligned.m16n8k16.row.col.f32.bf16.bf16.f32 "        \
        "{%0,%1,%2,%3}, {%4,%5,%6,%7}, {%8,%9}, {%0,%1,%2,%3};"                \
        : "+f"((d)[0]), "+f"((d)[1]), "+f"((d)[2]), "+f"((d)[3])               \
        : "r"(a0), "r"(a1), "r"(a2), "r"(a3), "r"(b0), "r"(b1))

__device__ __forceinline__ uint32_t packbf(float lo, float hi) {
    uint32_t r;
    asm("cvt.rn.bf16x2.f32 %0, %1, %2;" : "=r"(r) : "f"(hi), "f"(lo));
    return r;
}

/* ================= split-bf16 tensor GEMM (cp.async pipelined) ===== */
#define KC      64
#define TILE_B  (128 * 128)
#define STAGE_B (4 * TILE_B)
#define GSM_TOTAL (2 * STAGE_B)

__device__ __forceinline__ void load_tiles_async(uint32_t sbase, int st,
    const __nv_bfloat16* Ah, const __nv_bfloat16* Al,
    const __nv_bfloat16* Bh, const __nv_bfloat16* Bl,
    int m0, int n0, int K, int k0)
{
    uint32_t base = sbase + st * STAGE_B;
    const int tid = threadIdx.x;
    const __nv_bfloat16* srcs[4] = {Ah, Al, Bh, Bl};
#pragma unroll
    for (int it = 0; it < 16; it++) {
        int gidx = tid + it * 256;
        int tile = gidx >> 10;
        int r    = (gidx >> 3) & 127;
        int s    = gidx & 7;
        int row0 = (tile < 2) ? m0 : n0;
        const __nv_bfloat16* src = srcs[tile] + (size_t)(row0 + r) * K + k0 + s * 8;
        uint32_t dst = base + tile * TILE_B + r * 128 + ((s ^ (r & 7)) << 4);
        CP_ASYNC16(dst, src);
    }
}

__global__ __launch_bounds__(256, 1) void tc_gemm(
    const __nv_bfloat16* __restrict__ Ah, const __nv_bfloat16* __restrict__ Al,
    const __nv_bfloat16* __restrict__ Bh, const __nv_bfloat16* __restrict__ Bl,
    float* __restrict__ C, int M, int N, int K)
{
    extern __shared__ char smem[];
    const int tid = threadIdx.x;
    const int wid = tid >> 5;
    const int lid = tid & 31;
    const int mw  = wid & 1;
    const int nw  = wid >> 1;
    const int m0  = blockIdx.y * 128;
    const int n0  = blockIdx.x * 128;

    const uint32_t sb = smem_u32(smem);

    float acc[4][4][4];
#pragma unroll
    for (int i = 0; i < 4; i++)
#pragma unroll
        for (int j = 0; j < 4; j++)
#pragma unroll
            for (int u = 0; u < 4; u++) acc[i][j][u] = 0.f;

    load_tiles_async(sb, 0, Ah, Al, Bh, Bl, m0, n0, K, 0);
    CP_COMMIT();

    const int nch = K / KC;
    for (int c = 0; c < nch; c++) {
        const int st = c & 1;
        if (c + 1 < nch) {
            load_tiles_async(sb, st ^ 1, Ah, Al, Bh, Bl, m0, n0, K, (c + 1) * KC);
            CP_COMMIT();
            CP_WAIT(1);
        } else {
            CP_WAIT(0);
        }
        __syncthreads();

        const uint32_t tAh = sb + st * STAGE_B + 0 * TILE_B;
        const uint32_t tAl = sb + st * STAGE_B + 1 * TILE_B;
        const uint32_t tBh = sb + st * STAGE_B + 2 * TILE_B;
        const uint32_t tBl = sb + st * STAGE_B + 3 * TILE_B;

#pragma unroll
        for (int kb = 0; kb < KC / 16; kb++) {
            uint32_t ah[4][4], al[4][4];
#pragma unroll
            for (int mf = 0; mf < 4; mf++) {
                int r = mw * 64 + mf * 16 + (lid & 15);
                int s = 2 * kb + (lid >> 4);
                uint32_t off = (uint32_t)(r * 128 + ((s ^ (r & 7)) << 4));
                LDSM_X4(ah[mf][0], ah[mf][1], ah[mf][2], ah[mf][3], tAh + off);
                LDSM_X4(al[mf][0], al[mf][1], al[mf][2], al[mf][3], tAl + off);
            }
            uint32_t bh[4][2], bl[4][2];
#pragma unroll
            for (int nb = 0; nb < 2; nb++) {
                int r = nw * 32 + nb * 16 + (lid & 15);
                int s = 2 * kb + (lid >> 4);
                uint32_t off = (uint32_t)(r * 128 + ((s ^ (r & 7)) << 4));
                uint32_t r0, r1, r2, r3;
                LDSM_X4(r0, r1, r2, r3, tBh + off);
                bh[2 * nb + 0][0] = r0; bh[2 * nb + 0][1] = r2;
                bh[2 * nb + 1][0] = r1; bh[2 * nb + 1][1] = r3;
                LDSM_X4(r0, r1, r2, r3, tBl + off);
                bl[2 * nb + 0][0] = r0; bl[2 * nb + 0][1] = r2;
                bl[2 * nb + 1][0] = r1; bl[2 * nb + 1][1] = r3;
            }
            /* split-passes: 16 independent accumulators per pass */
#pragma unroll
            for (int mf = 0; mf < 4; mf++)
#pragma unroll
                for (int j = 0; j < 4; j++)
                    MMA16816(acc[mf][j], ah[mf][0], ah[mf][1], ah[mf][2], ah[mf][3],
                             bh[j][0], bh[j][1]);
#pragma unroll
            for (int mf = 0; mf < 4; mf++)
#pragma unroll
                for (int j = 0; j < 4; j++)
                    MMA16816(acc[mf][j], ah[mf][0], ah[mf][1], ah[mf][2], ah[mf][3],
                             bl[j][0], bl[j][1]);
#pragma unroll
            for (int mf = 0; mf < 4; mf++)
#pragma unroll
                for (int j = 0; j < 4; j++)
                    MMA16816(acc[mf][j], al[mf][0], al[mf][1], al[mf][2], al[mf][3],
                             bh[j][0], bh[j][1]);
        }
        __syncthreads();
    }

#pragma unroll
    for (int mf = 0; mf < 4; mf++) {
        int rbase = m0 + mw * 64 + mf * 16 + (lid >> 2);
#pragma unroll
        for (int j = 0; j < 4; j++) {
            int col = n0 + nw * 32 + j * 8 + 2 * (lid & 3);
            *(float2*)&C[(size_t)rbase * N + col] =
                make_float2(acc[mf][j][0], acc[mf][j][1]);
            *(float2*)&C[(size_t)(rbase + 8) * N + col] =
                make_float2(acc[mf][j][2], acc[mf][j][3]);
        }
    }
}

/* ================= split conversion kernels ======================== */
__global__ __launch_bounds__(256) void cvt_split(const float* __restrict__ x,
                                                 __nv_bfloat16* __restrict__ h,
                                                 __nv_bfloat16* __restrict__ l,
                                                 int n)
{
    int i = (blockIdx.x * 256 + threadIdx.x) * 4;
    if (i >= n) return;
    float4 v = *(const float4*)(x + i);
    float vv[4] = {v.x, v.y, v.z, v.w};
    __nv_bfloat16 hh[4], ll[4];
#pragma unroll
    for (int j = 0; j < 4; j++) {
        hh[j] = __float2bfloat16(vv[j]);
        ll[j] = __float2bfloat16(vv[j] - __bfloat162float(hh[j]));
    }
    *(uint2*)(h + i) = *(uint2*)hh;
    *(uint2*)(l + i) = *(uint2*)ll;
}

__global__ void cvt_split_t(const float* __restrict__ x,
                            __nv_bfloat16* __restrict__ th,
                            __nv_bfloat16* __restrict__ tl,
                            int R, int C)
{
    __shared__ float t[32][33];
    const int bx = blockIdx.x * 32;
    const int by = blockIdx.y * 32;
    const int tx = threadIdx.x, ty = threadIdx.y;
#pragma unroll
    for (int j = 0; j < 32; j += 8)
        t[ty + j][tx] = x[(size_t)(by + ty + j) * C + bx + tx];
    __syncthreads();
#pragma unroll
    for (int j = 0; j < 32; j += 8) {
        float v = t[tx][ty + j];
        __nv_bfloat16 hh = __float2bfloat16(v);
        float lo = v - __bfloat162float(hh);
        size_t o = (size_t)(bx + ty + j) * R + by + tx;
        th[o] = hh;
        tl[o] = __float2bfloat16(lo);
    }
}

/* ---------------- inv_freq table (fp64 pow once) -------------------- */
__global__ void init_freq()
{
    int d = threadIdx.x;
    g_invfreq[d] = (float)(1.0 / pow(1000000.0, (double)d / (double)(D / 2)));
}

/* ---------------- RMSNorm + RoPE + bf16 split ----------------------- */
__global__ __launch_bounds__(128) void normrope_kernel(const int* __restrict__ positions,
                                                       const float* __restrict__ q_norm_w,
                                                       const float* __restrict__ k_norm_w,
                                                       int T)
{
    const int t = blockIdx.x;
    const int h = blockIdx.y;
    const int d = threadIdx.x;

    if (h >= NH + NKV) {                       /* V: split only */
        int hv = h - NH - NKV;
        float v = g_qkv[(size_t)t * QKV_N + (NH + NKV) * D + hv * D + d];
        __nv_bfloat16 hh = __float2bfloat16(v);
        size_t o = ((size_t)t * NKV + hv) * D + d;
        g_vh[o] = hh;
        g_vl[o] = __float2bfloat16(v - __bfloat162float(hh));
        return;
    }

    const float* src;
    const float* w;
    __nv_bfloat16 *dsth, *dstl;
    float sc;
    if (h < NH) {
        src = g_qkv + (size_t)t * QKV_N + h * D;
        w = q_norm_w;
        dsth = g_qh + ((size_t)t * NH + h) * D;
        dstl = g_ql + ((size_t)t * NH + h) * D;
        sc = 0.08838834764831845f;
    } else {
        int hk = h - NH;
        src = g_qkv + (size_t)t * QKV_N + NH * D + hk * D;
        w = k_norm_w;
        dsth = g_kh + ((size_t)t * NKV + hk) * D;
        dstl = g_kl + ((size_t)t * NKV + hk) * D;
        sc = 1.0f;
    }

    float x = src[d];
    float ss = x * x;
#pragma unroll
    for (int o = 16; o > 0; o >>= 1) ss += __shfl_xor_sync(0xFFFFFFFFu, ss, o);

    __shared__ float red[4];
    __shared__ float s[D];
    if ((d & 31) == 0) red[d >> 5] = ss;
    __syncthreads();
    float var = (red[0] + red[1] + red[2] + red[3]) * (1.0f / (float)D);
    float nx = x * rsqrtf(var + 1e-6f) * w[d];
    s[d] = nx;
    __syncthreads();

    if (d < D / 2) {
        float p = (float)positions[t];
        float ang = p * g_invfreq[d];
        float c = cosf(ang);
        float si = sinf(ang);
        float x1 = s[d];
        float x2 = s[d + D / 2];
        float y1 = (x1 * c - x2 * si) * sc;
        float y2 = (x2 * c + x1 * si) * sc;
        __nv_bfloat16 h1 = __float2bfloat16(y1);
        __nv_bfloat16 h2 = __float2bfloat16(y2);
        dsth[d]         = h1;
        dsth[d + D / 2] = h2;
        dstl[d]         = __float2bfloat16(y1 - __bfloat162float(h1));
        dstl[d + D / 2] = __float2bfloat16(y2 - __bfloat162float(h2));
    }
}

/* ---------------- causal flash attention (mma.sync, split bf16) ----- */
#define A_QH 0
#define A_QL 16384
#define A_KH 32768
#define A_KL 49152
#define A_VH 65536
#define A_VL 81920
#define ASM_TOTAL 98304

__global__ __launch_bounds__(128) void attn_kernel(int T_)
{
    extern __shared__ char asmem[];
    const uint32_t sb = smem_u32(asmem);

    const int h   = blockIdx.y;
    const int hk  = h >> 1;
    const int bi  = gridDim.x - 1 - blockIdx.x;
    const int m0  = bi * 64;
    const int tid = threadIdx.x;
    const int wid = tid >> 5;
    const int lid = tid & 31;
    const int wrow = wid * 16;

    /* load Q tiles (qh, ql) via cp.async */
#pragma unroll
    for (int it = 0; it < 8; it++) {
        int idx = tid + it * 128;
        int r = idx >> 4, s = idx & 15;
        uint32_t off = (uint32_t)(r * 256 + ((s ^ (r & 7)) << 4));
        size_t g = ((size_t)(m0 + r) * NH + h) * D + s * 8;
        CP_ASYNC16(sb + A_QH + off, g_qh + g);
        CP_ASYNC16(sb + A_QL + off, g_ql + g);
    }
    CP_COMMIT();

    float o[16][4];
#pragma unroll
    for (int i = 0; i < 16; i++)
#pragma unroll
        for (int u = 0; u < 4; u++) o[i][u] = 0.f;

    const int r0g = m0 + wrow + (lid >> 2);
    const int r1g = r0g + 8;
    float mrow0 = -1e30f, mrow1 = -1e30f;
    float lsum0 = 0.f, lsum1 = 0.f;

    const int ntiles = bi + 1;
    for (int kt = 0; kt < ntiles; kt++) {
        const int k0 = kt * 64;
        __syncthreads();
#pragma unroll
        for (int it = 0; it < 8; it++) {
            int idx = tid + it * 128;
            int r = idx >> 4, s = idx & 15;
            uint32_t off = (uint32_t)(r * 256 + ((s ^ (r & 7)) << 4));
            size_t g = ((size_t)(k0 + r) * NKV + hk) * D + s * 8;
            CP_ASYNC16(sb + A_KH + off, g_kh + g);
            CP_ASYNC16(sb + A_KL + off, g_kl + g);
            CP_ASYNC16(sb + A_VH + off, g_vh + g);
            CP_ASYNC16(sb + A_VL + off, g_vl + g);
        }
        CP_COMMIT();
        CP_WAIT(0);
        __syncthreads();

        /* ---- S = Q K^T (split-passes, independent accs) ---- */
        float sa[8][4];
#pragma unroll
        for (int nb = 0; nb < 8; nb++)
#pragma unroll
            for (int u = 0; u < 4; u++) sa[nb][u] = 0.f;

#pragma unroll
        for (int kb = 0; kb < 8; kb++) {
            int qr = wrow + (lid & 15);
            int qs = 2 * kb + (lid >> 4);
            uint32_t qoff = (uint32_t)(qr * 256 + ((qs ^ (qr & 7)) << 4));
            uint32_t qh0, qh1, qh2, qh3, ql0, ql1, ql2, ql3;
            LDSM_X4(qh0, qh1, qh2, qh3, sb + A_QH + qoff);
            LDSM_X4(ql0, ql1, ql2, ql3, sb + A_QL + qoff);

            uint32_t kh[4][4], kl[4][4];
#pragma unroll
            for (int nb16 = 0; nb16 < 4; nb16++) {
                int kr = nb16 * 16 + (lid & 15);
                int ks = 2 * kb + (lid >> 4);
                uint32_t koff = (uint32_t)(kr * 256 + ((ks ^ (kr & 7)) << 4));
                LDSM_X4(kh[nb16][0], kh[nb16][1], kh[nb16][2], kh[nb16][3], sb + A_KH + koff);
                LDSM_X4(kl[nb16][0], kl[nb16][1], kl[nb16][2], kl[nb16][3], sb + A_KL + koff);
            }
#pragma unroll
            for (int nb16 = 0; nb16 < 4; nb16++) {
                MMA16816(sa[2 * nb16 + 0], qh0, qh1, qh2, qh3, kh[nb16][0], kh[nb16][2]);
                MMA16816(sa[2 * nb16 + 1], qh0, qh1, qh2, qh3, kh[nb16][1], kh[nb16][3]);
            }
#pragma unroll
            for (int nb16 = 0; nb16 < 4; nb16++) {
                MMA16816(sa[2 * nb16 + 0], qh0, qh1, qh2, qh3, kl[nb16][0], kl[nb16][2]);
                MMA16816(sa[2 * nb16 + 1], qh0, qh1, qh2, qh3, kl[nb16][1], kl[nb16][3]);
            }
#pragma unroll
            for (int nb16 = 0; nb16 < 4; nb16++) {
                MMA16816(sa[2 * nb16 + 0], ql0, ql1, ql2, ql3, kh[nb16][0], kh[nb16][2]);
                MMA16816(sa[2 * nb16 + 1], ql0, ql1, ql2, ql3, kh[nb16][1], kh[nb16][3]);
            }
        }

        /* ---- mask + online softmax ---- */
        float mx0 = mrow0, mx1 = mrow1;
#pragma unroll
        for (int nb = 0; nb < 8; nb++) {
            int col = k0 + nb * 8 + 2 * (lid & 3);
            if (col > r0g)     sa[nb][0] = -1e30f;
            if (col + 1 > r0g) sa[nb][1] = -1e30f;
            if (col > r1g)     sa[nb][2] = -1e30f;
            if (col + 1 > r1g) sa[nb][3] = -1e30f;
            mx0 = fmaxf(mx0, fmaxf(sa[nb][0], sa[nb][1]));
            mx1 = fmaxf(mx1, fmaxf(sa[nb][2], sa[nb][3]));
        }
        mx0 = fmaxf(mx0, __shfl_xor_sync(0xFFFFFFFFu, mx0, 1));
        mx0 = fmaxf(mx0, __shfl_xor_sync(0xFFFFFFFFu, mx0, 2));
        mx1 = fmaxf(mx1, __shfl_xor_sync(0xFFFFFFFFu, mx1, 1));
        mx1 = fmaxf(mx1, __shfl_xor_sync(0xFFFFFFFFu, mx1, 2));

        float corr0 = __expf(mrow0 - mx0);
        float corr1 = __expf(mrow1 - mx1);
        mrow0 = mx0; mrow1 = mx1;

        float ps0 = 0.f, ps1 = 0.f;
#pragma unroll
        for (int nb = 0; nb < 8; nb++) {
            sa[nb][0] = __expf(sa[nb][0] - mx0);
            sa[nb][1] = __expf(sa[nb][1] - mx0);
            sa[nb][2] = __expf(sa[nb][2] - mx1);
            sa[nb][3] = __expf(sa[nb][3] - mx1);
            ps0 += sa[nb][0] + sa[nb][1];
            ps1 += sa[nb][2] + sa[nb][3];
        }
        ps0 += __shfl_xor_sync(0xFFFFFFFFu, ps0, 1);
        ps0 += __shfl_xor_sync(0xFFFFFFFFu, ps0, 2);
        ps1 += __shfl_xor_sync(0xFFFFFFFFu, ps1, 1);
        ps1 += __shfl_xor_sync(0xFFFFFFFFu, ps1, 2);
        lsum0 = lsum0 * corr0 + ps0;
        lsum1 = lsum1 * corr1 + ps1;

#pragma unroll
        for (int i = 0; i < 16; i++) {
            o[i][0] *= corr0; o[i][1] *= corr0;
            o[i][2] *= corr1; o[i][3] *= corr1;
        }

        /* ---- O += P V (dn pairs; split-passes over 4 accs) ---- */
#pragma unroll
        for (int jb = 0; jb < 4; jb++) {
            float p00 = sa[2 * jb][0],     p01 = sa[2 * jb][1];
            float p02 = sa[2 * jb][2],     p03 = sa[2 * jb][3];
            float p10 = sa[2 * jb + 1][0], p11 = sa[2 * jb + 1][1];
            float p12 = sa[2 * jb + 1][2], p13 = sa[2 * jb + 1][3];
            uint32_t ph0 = packbf(p00, p01), ph1 = packbf(p02, p03);
            uint32_t ph2 = packbf(p10, p11), ph3 = packbf(p12, p13);
            uint32_t pl0 = packbf(p00 - __bfloat162float(__float2bfloat16(p00)),
                                  p01 - __bfloat162float(__float2bfloat16(p01)));
            uint32_t pl1 = packbf(p02 - __bfloat162float(__float2bfloat16(p02)),
                                  p03 - __bfloat162float(__float2bfloat16(p03)));
            uint32_t pl2 = packbf(p10 - __bfloat162float(__float2bfloat16(p10)),
                                  p11 - __bfloat162float(__float2bfloat16(p11)));
            uint32_t pl3 = packbf(p12 - __bfloat162float(__float2bfloat16(p12)),
                                  p13 - __bfloat162float(__float2bfloat16(p13)));

            int m = lid >> 3;
            int vr = jb * 16 + (lid & 7) + 8 * (m & 1);
#pragma unroll
            for (int dp = 0; dp < 4; dp++) {
                int dn0 = 2 * dp, dn1 = 2 * dp + 1;
                int vs0 = 2 * dn0 + (m >> 1);
                int vs1 = 2 * dn1 + (m >> 1);
                uint32_t voff0 = (uint32_t)(vr * 256 + ((vs0 ^ (vr & 7)) << 4));
                uint32_t voff1 = (uint32_t)(vr * 256 + ((vs1 ^ (vr & 7)) << 4));
                uint32_t vA[4], vB[4], wA[4], wB[4];
                LDSM_X4_T(vA[0], vA[1], vA[2], vA[3], sb + A_VH + voff0);
                LDSM_X4_T(vB[0], vB[1], vB[2], vB[3], sb + A_VH + voff1);
                LDSM_X4_T(wA[0], wA[1], wA[2], wA[3], sb + A_VL + voff0);
                LDSM_X4_T(wB[0], wB[1], wB[2], wB[3], sb + A_VL + voff1);
                /* pass 1: Ph * Vh */
                MMA16816(o[2 * dn0 + 0], ph0, ph1, ph2, ph3, vA[0], vA[1]);
                MMA16816(o[2 * dn0 + 1], ph0, ph1, ph2, ph3, vA[2], vA[3]);
                MMA16816(o[2 * dn1 + 0], ph0, ph1, ph2, ph3, vB[0], vB[1]);
                MMA16816(o[2 * dn1 + 1], ph0, ph1, ph2, ph3, vB[2], vB[3]);
                /* pass 2: Ph * Vl */
                MMA16816(o[2 * dn0 + 0], ph0, ph1, ph2, ph3, wA[0], wA[1]);
                MMA16816(o[2 * dn0 + 1], ph0, ph1, ph2, ph3, wA[2], wA[3]);
                MMA16816(o[2 * dn1 + 0], ph0, ph1, ph2, ph3, wB[0], wB[1]);
                MMA16816(o[2 * dn1 + 1], ph0, ph1, ph2, ph3, wB[2], wB[3]);
                /* pass 3: Pl * Vh */
                MMA16816(o[2 * dn0 + 0], pl0, pl1, pl2, pl3, vA[0], vA[1]);
                MMA16816(o[2 * dn0 + 1], pl0, pl1, pl2, pl3, vA[2], vA[3]);
                MMA16816(o[2 * dn1 + 0], pl0, pl1, pl2, pl3, vB[0], vB[1]);
                MMA16816(o[2 * dn1 + 1], pl0, pl1, pl2, pl3, vB[2], vB[3]);
            }
        }
    }

    /* epilogue: normalize, split to bf16 h/l, store */
    const float inv0 = 1.f / lsum0;
    const float inv1 = 1.f / lsum1;
#pragma unroll
    for (int dn = 0; dn < 16; dn++) {
        int col = dn * 8 + 2 * (lid & 3);
        float a0 = o[dn][0] * inv0, a1 = o[dn][1] * inv0;
        float b0 = o[dn][2] * inv1, b1 = o[dn][3] * inv1;
        __nv_bfloat16 ha0 = __float2bfloat16(a0), ha1 = __float2bfloat16(a1);
        __nv_bfloat16 hb0 = __float2bfloat16(b0), hb1 = __float2bfloat16(b1);
        uint32_t hA = packbf(a0, a1);
        uint32_t lA = packbf(a0 - __bfloat162float(ha0), a1 - __bfloat162float(ha1));
        uint32_t hB = packbf(b0, b1);
        uint32_t lB = packbf(b0 - __bfloat162float(hb0), b1 - __bfloat162float(hb1));
        size_t iA = (size_t)r0g * (NH * D) + h * D + col;
        size_t iB = (size_t)r1g * (NH * D) + h * D + col;
        *(uint32_t*)(g_oth + iA) = hA;
        *(uint32_t*)(g_otl + iA) = lA;
        *(uint32_t*)(g_oth + iB) = hB;
        *(uint32_t*)(g_otl + iB) = lB;
    }
}

/* ---------------- launch -------------------------------------------- */
extern "C" void kernel_launch(void* const* d_in, const int* in_sizes, int n_in,
                              void* d_out, int out_size)
{
    const int*   positions = (const int*)d_in[0];
    const float* hidden    = (const float*)d_in[1];
    const float* w_qkv     = (const float*)d_in[2];
    const float* q_norm_w  = (const float*)d_in[3];
    const float* k_norm_w  = (const float*)d_in[4];
    const float* w_o       = (const float*)d_in[5];
    float*       out       = (float*)d_out;
    const int    T         = in_sizes[0];   /* 2048 */

    __nv_bfloat16 *ah, *al, *wqh, *wql, *oh, *ol, *woh, *wol;
    cudaGetSymbolAddress((void**)&ah,  g_ah);
    cudaGetSymbolAddress((void**)&al,  g_al);
    cudaGetSymbolAddress((void**)&wqh, g_wqt_h);
    cudaGetSymbolAddress((void**)&wql, g_wqt_l);
    cudaGetSymbolAddress((void**)&oh,  g_oth);
    cudaGetSymbolAddress((void**)&ol,  g_otl);
    cudaGetSymbolAddress((void**)&woh, g_wot_h);
    cudaGetSymbolAddress((void**)&wol, g_wot_l);

    cudaFuncSetAttribute(tc_gemm, cudaFuncAttributeMaxDynamicSharedMemorySize, GSM_TOTAL);
    cudaFuncSetAttribute(attn_kernel, cudaFuncAttributeMaxDynamicSharedMemorySize, ASM_TOTAL);

    /* 0) inv_freq table + input splits */
    init_freq<<<1, D / 2>>>();
    cvt_split<<<(T * HID) / 1024, 256>>>(hidden, ah, al, T * HID);
    cvt_split_t<<<dim3(QKV_N / 32, HID / 32), dim3(32, 8)>>>(w_qkv, wqh, wql, HID, QKV_N);

    /* 1) QKV projection */
    {
        float* cq;
        cudaGetSymbolAddress((void**)&cq, g_qkv);
        dim3 g(QKV_N / 128, T / 128);
        tc_gemm<<<g, 256, GSM_TOTAL>>>(ah, al, wqh, wql, cq, T, QKV_N, HID);
    }

    /* 2) RMSNorm + RoPE + bf16 splits for q/k/v */
    dim3 g2(T, NH + 2 * NKV);
    normrope_kernel<<<g2, 128>>>(positions, q_norm_w, k_norm_w, T);

    /* 3) causal GQA flash attention */
    dim3 g3(T / 64, NH);
    attn_kernel<<<g3, 128, ASM_TOTAL>>>(T);

    /* 4) output projection */
    cvt_split_t<<<dim3(HID / 32, (NH * D) / 32), dim3(32, 8)>>>(w_o, woh, wol, NH * D, HID);
    {
        dim3 g(HID / 128, T / 128);
        tc_gemm<<<g, 256, GSM_TOTAL>>>(oh, ol, woh, wol, out, T, HID, HID);
    }
}

// round 11
// speedup vs baseline: 5.0245x; 1.0244x over previous
#include <cuda_runtime.h>
#include <cuda_bf16.h>
#include <stdint.h>
#include <math.h>

#define NH   16
#define NKV  8
#define D    128
#define HID  2048
#define QKV_N ((NH + 2 * NKV) * D)   /* 4096 */
#define MAXT 2048

/* ---------------- scratch (no allocations allowed) ---------------- */
__device__ float g_qkv [(size_t)MAXT * QKV_N];
__device__ float g_invfreq[D / 2];

/* split-bf16 operands */
__device__ __nv_bfloat16 g_ah  [(size_t)MAXT * HID];
__device__ __nv_bfloat16 g_al  [(size_t)MAXT * HID];
__device__ __nv_bfloat16 g_wqt_h[(size_t)QKV_N * HID];
__device__ __nv_bfloat16 g_wqt_l[(size_t)QKV_N * HID];
__device__ __nv_bfloat16 g_wot_h[(size_t)HID * HID];
__device__ __nv_bfloat16 g_wot_l[(size_t)HID * HID];

/* attention operands / outputs (all compensated bf16 splits) */
__device__ __nv_bfloat16 g_qh[(size_t)MAXT * NH  * D];
__device__ __nv_bfloat16 g_ql[(size_t)MAXT * NH  * D];
__device__ __nv_bfloat16 g_kh[(size_t)MAXT * NKV * D];
__device__ __nv_bfloat16 g_kl[(size_t)MAXT * NKV * D];
__device__ __nv_bfloat16 g_vh[(size_t)MAXT * NKV * D];
__device__ __nv_bfloat16 g_vl[(size_t)MAXT * NKV * D];
__device__ __nv_bfloat16 g_oth[(size_t)MAXT * NH * D];
__device__ __nv_bfloat16 g_otl[(size_t)MAXT * NH * D];

/* ================= helpers ========================================= */
__device__ __forceinline__ uint32_t smem_u32(const void* p) {
    uint32_t a;
    asm("{ .reg .u64 t; cvta.to.shared.u64 t, %1; cvt.u32.u64 %0, t; }"
        : "=r"(a) : "l"(p));
    return a;
}

#define CP_ASYNC16(dst, src)                                                   \
    asm volatile("cp.async.cg.shared.global [%0], [%1], 16;"                   \
        :: "r"(dst), "l"(src))
#define CP_COMMIT() asm volatile("cp.async.commit_group;" ::: "memory")
#define CP_WAIT(n)  asm volatile("cp.async.wait_group %0;" :: "n"(n) : "memory")

#define LDSM_X4(r0, r1, r2, r3, addr)                                          \
    asm volatile("ldmatrix.sync.aligned.m8n8.x4.shared.b16 {%0,%1,%2,%3}, [%4];" \
        : "=r"(r0), "=r"(r1), "=r"(r2), "=r"(r3) : "r"(addr))

#define LDSM_X4_T(r0, r1, r2, r3, addr)                                        \
    asm volatile("ldmatrix.sync.aligned.m8n8.x4.trans.shared.b16 {%0,%1,%2,%3}, [%4];" \
        : "=r"(r0), "=r"(r1), "=r"(r2), "=r"(r3) : "r"(addr))

#define MMA16816(d, a0, a1, a2, a3, b0, b1)                                    \
    asm volatile("mma.sync.aligned.m16n8k16.row.col.f32.bf16.bf16.f32 "        \
        "{%0,%1,%2,%3}, {%4,%5,%6,%7}, {%8,%9}, {%0,%1,%2,%3};"                \
        : "+f"((d)[0]), "+f"((d)[1]), "+f"((d)[2]), "+f"((d)[3])               \
        : "r"(a0), "r"(a1), "r"(a2), "r"(a3), "r"(b0), "r"(b1))

__device__ __forceinline__ uint32_t packbf(float lo, float hi) {
    uint32_t r;
    asm("cvt.rn.bf16x2.f32 %0, %1, %2;" : "=r"(r) : "f"(hi), "f"(lo));
    return r;
}

/* ================= split-bf16 tensor GEMM ==========================
   KC=32, 3-stage cp.async pipeline, 96KB smem -> 2 CTAs/SM.
   Tile (128 rows x 32 cols bf16) stored as 64 physical rows x 128B:
   logical (r, seg s in 0..3) -> (r&63)*128 + (((s | ((r>>6)<<2)) ^ (r&7))<<4) */
#define KC      32
#define TILE_B  (64 * 128)             /* 8 KB  */
#define STAGE_B (4 * TILE_B)           /* 32 KB */
#define NSTAGE  3
#define GSM_TOTAL (NSTAGE * STAGE_B)   /* 96 KB */

__device__ __forceinline__ uint32_t tile_off(int r, int s) {
    return (uint32_t)((r & 63) * 128 + (((s | ((r >> 6) << 2)) ^ (r & 7)) << 4));
}

__device__ __forceinline__ void load_tiles_async(uint32_t sbase, int st,
    const __nv_bfloat16* Ah, const __nv_bfloat16* Al,
    const __nv_bfloat16* Bh, const __nv_bfloat16* Bl,
    int m0, int n0, int K, int k0)
{
    uint32_t base = sbase + st * STAGE_B;
    const int tid = threadIdx.x;
    const __nv_bfloat16* srcs[4] = {Ah, Al, Bh, Bl};
#pragma unroll
    for (int it = 0; it < 8; it++) {
        int gidx = tid + it * 256;         /* 0..2047 */
        int tile = gidx >> 9;
        int r    = (gidx >> 2) & 127;
        int s    = gidx & 3;
        int row0 = (tile < 2) ? m0 : n0;
        const __nv_bfloat16* src = srcs[tile] + (size_t)(row0 + r) * K + k0 + s * 8;
        CP_ASYNC16(base + tile * TILE_B + tile_off(r, s), src);
    }
}

__global__ __launch_bounds__(256, 2) void tc_gemm(
    const __nv_bfloat16* __restrict__ Ah, const __nv_bfloat16* __restrict__ Al,
    const __nv_bfloat16* __restrict__ Bh, const __nv_bfloat16* __restrict__ Bl,
    float* __restrict__ C, int M, int N, int K)
{
    extern __shared__ char smem[];
    const int tid = threadIdx.x;
    const int wid = tid >> 5;
    const int lid = tid & 31;
    const int mw  = wid & 1;
    const int nw  = wid >> 1;
    const int m0  = blockIdx.y * 128;
    const int n0  = blockIdx.x * 128;

    const uint32_t sb = smem_u32(smem);

    float acc[4][4][4];
#pragma unroll
    for (int i = 0; i < 4; i++)
#pragma unroll
        for (int j = 0; j < 4; j++)
#pragma unroll
            for (int u = 0; u < 4; u++) acc[i][j][u] = 0.f;

    const int nch = K / KC;
    load_tiles_async(sb, 0, Ah, Al, Bh, Bl, m0, n0, K, 0);
    CP_COMMIT();
    if (nch > 1) {
        load_tiles_async(sb, 1, Ah, Al, Bh, Bl, m0, n0, K, KC);
        CP_COMMIT();
    }

    int st = 0;
    for (int c = 0; c < nch; c++) {
        if (c + 2 < nch) {
            int st2 = (st + 2) % NSTAGE;
            load_tiles_async(sb, st2, Ah, Al, Bh, Bl, m0, n0, K, (c + 2) * KC);
            CP_COMMIT();
            CP_WAIT(2);
        } else if (c + 1 < nch) {
            CP_WAIT(1);
        } else {
            CP_WAIT(0);
        }
        __syncthreads();

        const uint32_t tAh = sb + st * STAGE_B + 0 * TILE_B;
        const uint32_t tAl = sb + st * STAGE_B + 1 * TILE_B;
        const uint32_t tBh = sb + st * STAGE_B + 2 * TILE_B;
        const uint32_t tBl = sb + st * STAGE_B + 3 * TILE_B;

#pragma unroll
        for (int kb = 0; kb < KC / 16; kb++) {
            const int sseg = 2 * kb + (lid >> 4);
            uint32_t ah[4][4], al[4][4];
#pragma unroll
            for (int mf = 0; mf < 4; mf++) {
                int r = mw * 64 + mf * 16 + (lid & 15);
                uint32_t off = tile_off(r, sseg);
                LDSM_X4(ah[mf][0], ah[mf][1], ah[mf][2], ah[mf][3], tAh + off);
                LDSM_X4(al[mf][0], al[mf][1], al[mf][2], al[mf][3], tAl + off);
            }
            uint32_t bh[4][2], bl[4][2];
#pragma unroll
            for (int nb = 0; nb < 2; nb++) {
                int r = nw * 32 + nb * 16 + (lid & 15);
                uint32_t off = tile_off(r, sseg);
                uint32_t r0, r1, r2, r3;
                LDSM_X4(r0, r1, r2, r3, tBh + off);
                bh[2 * nb + 0][0] = r0; bh[2 * nb + 0][1] = r2;
                bh[2 * nb + 1][0] = r1; bh[2 * nb + 1][1] = r3;
                LDSM_X4(r0, r1, r2, r3, tBl + off);
                bl[2 * nb + 0][0] = r0; bl[2 * nb + 0][1] = r2;
                bl[2 * nb + 1][0] = r1; bl[2 * nb + 1][1] = r3;
            }
#pragma unroll
            for (int mf = 0; mf < 4; mf++)
#pragma unroll
                for (int j = 0; j < 4; j++)
                    MMA16816(acc[mf][j], ah[mf][0], ah[mf][1], ah[mf][2], ah[mf][3],
                             bh[j][0], bh[j][1]);
#pragma unroll
            for (int mf = 0; mf < 4; mf++)
#pragma unroll
                for (int j = 0; j < 4; j++)
                    MMA16816(acc[mf][j], ah[mf][0], ah[mf][1], ah[mf][2], ah[mf][3],
                             bl[j][0], bl[j][1]);
#pragma unroll
            for (int mf = 0; mf < 4; mf++)
#pragma unroll
                for (int j = 0; j < 4; j++)
                    MMA16816(acc[mf][j], al[mf][0], al[mf][1], al[mf][2], al[mf][3],
                             bh[j][0], bh[j][1]);
        }
        __syncthreads();
        st = (st + 1) % NSTAGE;
    }

#pragma unroll
    for (int mf = 0; mf < 4; mf++) {
        int rbase = m0 + mw * 64 + mf * 16 + (lid >> 2);
#pragma unroll
        for (int j = 0; j < 4; j++) {
            int col = n0 + nw * 32 + j * 8 + 2 * (lid & 3);
            *(float2*)&C[(size_t)rbase * N + col] =
                make_float2(acc[mf][j][0], acc[mf][j][1]);
            *(float2*)&C[(size_t)(rbase + 8) * N + col] =
                make_float2(acc[mf][j][2], acc[mf][j][3]);
        }
    }
}

/* ================= split conversion kernels ======================== */
__global__ __launch_bounds__(256) void cvt_split(const float* __restrict__ x,
                                                 __nv_bfloat16* __restrict__ h,
                                                 __nv_bfloat16* __restrict__ l,
                                                 int n)
{
    int i = (blockIdx.x * 256 + threadIdx.x) * 4;
    if (i >= n) return;
    float4 v = *(const float4*)(x + i);
    float vv[4] = {v.x, v.y, v.z, v.w};
    __nv_bfloat16 hh[4], ll[4];
#pragma unroll
    for (int j = 0; j < 4; j++) {
        hh[j] = __float2bfloat16(vv[j]);
        ll[j] = __float2bfloat16(vv[j] - __bfloat162float(hh[j]));
    }
    *(uint2*)(h + i) = *(uint2*)hh;
    *(uint2*)(l + i) = *(uint2*)ll;
}

__global__ void cvt_split_t(const float* __restrict__ x,
                            __nv_bfloat16* __restrict__ th,
                            __nv_bfloat16* __restrict__ tl,
                            int R, int C)
{
    __shared__ float t[32][33];
    const int bx = blockIdx.x * 32;
    const int by = blockIdx.y * 32;
    const int tx = threadIdx.x, ty = threadIdx.y;
#pragma unroll
    for (int j = 0; j < 32; j += 8)
        t[ty + j][tx] = x[(size_t)(by + ty + j) * C + bx + tx];
    __syncthreads();
#pragma unroll
    for (int j = 0; j < 32; j += 8) {
        float v = t[tx][ty + j];
        __nv_bfloat16 hh = __float2bfloat16(v);
        float lo = v - __bfloat162float(hh);
        size_t o = (size_t)(bx + ty + j) * R + by + tx;
        th[o] = hh;
        tl[o] = __float2bfloat16(lo);
    }
}

/* ---------------- inv_freq table (fp64 pow once) -------------------- */
__global__ void init_freq()
{
    int d = threadIdx.x;
    g_invfreq[d] = (float)(1.0 / pow(1000000.0, (double)d / (double)(D / 2)));
}

/* ---------------- RMSNorm + RoPE + bf16 split ----------------------- */
__global__ __launch_bounds__(128) void normrope_kernel(const int* __restrict__ positions,
                                                       const float* __restrict__ q_norm_w,
                                                       const float* __restrict__ k_norm_w,
                                                       int T)
{
    const int t = blockIdx.x;
    const int h = blockIdx.y;
    const int d = threadIdx.x;

    if (h >= NH + NKV) {                       /* V: split only */
        int hv = h - NH - NKV;
        float v = g_qkv[(size_t)t * QKV_N + (NH + NKV) * D + hv * D + d];
        __nv_bfloat16 hh = __float2bfloat16(v);
        size_t o = ((size_t)t * NKV + hv) * D + d;
        g_vh[o] = hh;
        g_vl[o] = __float2bfloat16(v - __bfloat162float(hh));
        return;
    }

    const float* src;
    const float* w;
    __nv_bfloat16 *dsth, *dstl;
    float sc;
    if (h < NH) {
        src = g_qkv + (size_t)t * QKV_N + h * D;
        w = q_norm_w;
        dsth = g_qh + ((size_t)t * NH + h) * D;
        dstl = g_ql + ((size_t)t * NH + h) * D;
        sc = 0.08838834764831845f;
    } else {
        int hk = h - NH;
        src = g_qkv + (size_t)t * QKV_N + NH * D + hk * D;
        w = k_norm_w;
        dsth = g_kh + ((size_t)t * NKV + hk) * D;
        dstl = g_kl + ((size_t)t * NKV + hk) * D;
        sc = 1.0f;
    }

    float x = src[d];
    float ss = x * x;
#pragma unroll
    for (int o = 16; o > 0; o >>= 1) ss += __shfl_xor_sync(0xFFFFFFFFu, ss, o);

    __shared__ float red[4];
    __shared__ float s[D];
    if ((d & 31) == 0) red[d >> 5] = ss;
    __syncthreads();
    float var = (red[0] + red[1] + red[2] + red[3]) * (1.0f / (float)D);
    float nx = x * rsqrtf(var + 1e-6f) * w[d];
    s[d] = nx;
    __syncthreads();

    if (d < D / 2) {
        float p = (float)positions[t];
        float ang = p * g_invfreq[d];
        float c = cosf(ang);
        float si = sinf(ang);
        float x1 = s[d];
        float x2 = s[d + D / 2];
        float y1 = (x1 * c - x2 * si) * sc;
        float y2 = (x2 * c + x1 * si) * sc;
        __nv_bfloat16 h1 = __float2bfloat16(y1);
        __nv_bfloat16 h2 = __float2bfloat16(y2);
        dsth[d]         = h1;
        dsth[d + D / 2] = h2;
        dstl[d]         = __float2bfloat16(y1 - __bfloat162float(h1));
        dstl[d + D / 2] = __float2bfloat16(y2 - __bfloat162float(h2));
    }
}

/* ---------------- causal flash attention (mma.sync, split bf16) ----- */
#define A_QH 0
#define A_QL 16384
#define A_KH 32768
#define A_KL 49152
#define A_VH 65536
#define A_VL 81920
#define ASM_TOTAL 98304

__global__ __launch_bounds__(128) void attn_kernel(int T_)
{
    extern __shared__ char asmem[];
    const uint32_t sb = smem_u32(asmem);

    const int h   = blockIdx.y;
    const int hk  = h >> 1;
    const int bi  = gridDim.x - 1 - blockIdx.x;
    const int m0  = bi * 64;
    const int tid = threadIdx.x;
    const int wid = tid >> 5;
    const int lid = tid & 31;
    const int wrow = wid * 16;

    /* load Q tiles (qh, ql) via cp.async */
#pragma unroll
    for (int it = 0; it < 8; it++) {
        int idx = tid + it * 128;
        int r = idx >> 4, s = idx & 15;
        uint32_t off = (uint32_t)(r * 256 + ((s ^ (r & 7)) << 4));
        size_t g = ((size_t)(m0 + r) * NH + h) * D + s * 8;
        CP_ASYNC16(sb + A_QH + off, g_qh + g);
        CP_ASYNC16(sb + A_QL + off, g_ql + g);
    }
    CP_COMMIT();

    float o[16][4];
#pragma unroll
    for (int i = 0; i < 16; i++)
#pragma unroll
        for (int u = 0; u < 4; u++) o[i][u] = 0.f;

    const int r0g = m0 + wrow + (lid >> 2);
    const int r1g = r0g + 8;
    float mrow0 = -1e30f, mrow1 = -1e30f;
    float lsum0 = 0.f, lsum1 = 0.f;

    const int ntiles = bi + 1;
    for (int kt = 0; kt < ntiles; kt++) {
        const int k0 = kt * 64;
        __syncthreads();
#pragma unroll
        for (int it = 0; it < 8; it++) {
            int idx = tid + it * 128;
            int r = idx >> 4, s = idx & 15;
            uint32_t off = (uint32_t)(r * 256 + ((s ^ (r & 7)) << 4));
            size_t g = ((size_t)(k0 + r) * NKV + hk) * D + s * 8;
            CP_ASYNC16(sb + A_KH + off, g_kh + g);
            CP_ASYNC16(sb + A_KL + off, g_kl + g);
            CP_ASYNC16(sb + A_VH + off, g_vh + g);
            CP_ASYNC16(sb + A_VL + off, g_vl + g);
        }
        CP_COMMIT();
        CP_WAIT(0);
        __syncthreads();

        /* ---- S = Q K^T (split-passes, independent accs) ---- */
        float sa[8][4];
#pragma unroll
        for (int nb = 0; nb < 8; nb++)
#pragma unroll
            for (int u = 0; u < 4; u++) sa[nb][u] = 0.f;

#pragma unroll
        for (int kb = 0; kb < 8; kb++) {
            int qr = wrow + (lid & 15);
            int qs = 2 * kb + (lid >> 4);
            uint32_t qoff = (uint32_t)(qr * 256 + ((qs ^ (qr & 7)) << 4));
            uint32_t qh0, qh1, qh2, qh3, ql0, ql1, ql2, ql3;
            LDSM_X4(qh0, qh1, qh2, qh3, sb + A_QH + qoff);
            LDSM_X4(ql0, ql1, ql2, ql3, sb + A_QL + qoff);

            uint32_t kh[4][4], kl[4][4];
#pragma unroll
            for (int nb16 = 0; nb16 < 4; nb16++) {
                int kr = nb16 * 16 + (lid & 15);
                int ks = 2 * kb + (lid >> 4);
                uint32_t koff = (uint32_t)(kr * 256 + ((ks ^ (kr & 7)) << 4));
                LDSM_X4(kh[nb16][0], kh[nb16][1], kh[nb16][2], kh[nb16][3], sb + A_KH + koff);
                LDSM_X4(kl[nb16][0], kl[nb16][1], kl[nb16][2], kl[nb16][3], sb + A_KL + koff);
            }
#pragma unroll
            for (int nb16 = 0; nb16 < 4; nb16++) {
                MMA16816(sa[2 * nb16 + 0], qh0, qh1, qh2, qh3, kh[nb16][0], kh[nb16][2]);
                MMA16816(sa[2 * nb16 + 1], qh0, qh1, qh2, qh3, kh[nb16][1], kh[nb16][3]);
            }
#pragma unroll
            for (int nb16 = 0; nb16 < 4; nb16++) {
                MMA16816(sa[2 * nb16 + 0], qh0, qh1, qh2, qh3, kl[nb16][0], kl[nb16][2]);
                MMA16816(sa[2 * nb16 + 1], qh0, qh1, qh2, qh3, kl[nb16][1], kl[nb16][3]);
            }
#pragma unroll
            for (int nb16 = 0; nb16 < 4; nb16++) {
                MMA16816(sa[2 * nb16 + 0], ql0, ql1, ql2, ql3, kh[nb16][0], kh[nb16][2]);
                MMA16816(sa[2 * nb16 + 1], ql0, ql1, ql2, ql3, kh[nb16][1], kh[nb16][3]);
            }
        }

        /* ---- mask + online softmax ---- */
        float mx0 = mrow0, mx1 = mrow1;
#pragma unroll
        for (int nb = 0; nb < 8; nb++) {
            int col = k0 + nb * 8 + 2 * (lid & 3);
            if (col > r0g)     sa[nb][0] = -1e30f;
            if (col + 1 > r0g) sa[nb][1] = -1e30f;
            if (col > r1g)     sa[nb][2] = -1e30f;
            if (col + 1 > r1g) sa[nb][3] = -1e30f;
            mx0 = fmaxf(mx0, fmaxf(sa[nb][0], sa[nb][1]));
            mx1 = fmaxf(mx1, fmaxf(sa[nb][2], sa[nb][3]));
        }
        mx0 = fmaxf(mx0, __shfl_xor_sync(0xFFFFFFFFu, mx0, 1));
        mx0 = fmaxf(mx0, __shfl_xor_sync(0xFFFFFFFFu, mx0, 2));
        mx1 = fmaxf(mx1, __shfl_xor_sync(0xFFFFFFFFu, mx1, 1));
        mx1 = fmaxf(mx1, __shfl_xor_sync(0xFFFFFFFFu, mx1, 2));

        float corr0 = __expf(mrow0 - mx0);
        float corr1 = __expf(mrow1 - mx1);
        mrow0 = mx0; mrow1 = mx1;

        float ps0 = 0.f, ps1 = 0.f;
#pragma unroll
        for (int nb = 0; nb < 8; nb++) {
            sa[nb][0] = __expf(sa[nb][0] - mx0);
            sa[nb][1] = __expf(sa[nb][1] - mx0);
            sa[nb][2] = __expf(sa[nb][2] - mx1);
            sa[nb][3] = __expf(sa[nb][3] - mx1);
            ps0 += sa[nb][0] + sa[nb][1];
            ps1 += sa[nb][2] + sa[nb][3];
        }
        ps0 += __shfl_xor_sync(0xFFFFFFFFu, ps0, 1);
        ps0 += __shfl_xor_sync(0xFFFFFFFFu, ps0, 2);
        ps1 += __shfl_xor_sync(0xFFFFFFFFu, ps1, 1);
        ps1 += __shfl_xor_sync(0xFFFFFFFFu, ps1, 2);
        lsum0 = lsum0 * corr0 + ps0;
        lsum1 = lsum1 * corr1 + ps1;

#pragma unroll
        for (int i = 0; i < 16; i++) {
            o[i][0] *= corr0; o[i][1] *= corr0;
            o[i][2] *= corr1; o[i][3] *= corr1;
        }

        /* ---- O += P V (dn pairs; split-passes over 4 accs) ---- */
#pragma unroll
        for (int jb = 0; jb < 4; jb++) {
            float p00 = sa[2 * jb][0],     p01 = sa[2 * jb][1];
            float p02 = sa[2 * jb][2],     p03 = sa[2 * jb][3];
            float p10 = sa[2 * jb + 1][0], p11 = sa[2 * jb + 1][1];
            float p12 = sa[2 * jb + 1][2], p13 = sa[2 * jb + 1][3];
            uint32_t ph0 = packbf(p00, p01), ph1 = packbf(p02, p03);
            uint32_t ph2 = packbf(p10, p11), ph3 = packbf(p12, p13);
            uint32_t pl0 = packbf(p00 - __bfloat162float(__float2bfloat16(p00)),
                                  p01 - __bfloat162float(__float2bfloat16(p01)));
            uint32_t pl1 = packbf(p02 - __bfloat162float(__float2bfloat16(p02)),
                                  p03 - __bfloat162float(__float2bfloat16(p03)));
            uint32_t pl2 = packbf(p10 - __bfloat162float(__float2bfloat16(p10)),
                                  p11 - __bfloat162float(__float2bfloat16(p11)));
            uint32_t pl3 = packbf(p12 - __bfloat162float(__float2bfloat16(p12)),
                                  p13 - __bfloat162float(__float2bfloat16(p13)));

            int m = lid >> 3;
            int vr = jb * 16 + (lid & 7) + 8 * (m & 1);
#pragma unroll
            for (int dp = 0; dp < 4; dp++) {
                int dn0 = 2 * dp, dn1 = 2 * dp + 1;
                int vs0 = 2 * dn0 + (m >> 1);
                int vs1 = 2 * dn1 + (m >> 1);
                uint32_t voff0 = (uint32_t)(vr * 256 + ((vs0 ^ (vr & 7)) << 4));
                uint32_t voff1 = (uint32_t)(vr * 256 + ((vs1 ^ (vr & 7)) << 4));
                uint32_t vA[4], vB[4], wA[4], wB[4];
                LDSM_X4_T(vA[0], vA[1], vA[2], vA[3], sb + A_VH + voff0);
                LDSM_X4_T(vB[0], vB[1], vB[2], vB[3], sb + A_VH + voff1);
                LDSM_X4_T(wA[0], wA[1], wA[2], wA[3], sb + A_VL + voff0);
                LDSM_X4_T(wB[0], wB[1], wB[2], wB[3], sb + A_VL + voff1);
                MMA16816(o[2 * dn0 + 0], ph0, ph1, ph2, ph3, vA[0], vA[1]);
                MMA16816(o[2 * dn0 + 1], ph0, ph1, ph2, ph3, vA[2], vA[3]);
                MMA16816(o[2 * dn1 + 0], ph0, ph1, ph2, ph3, vB[0], vB[1]);
                MMA16816(o[2 * dn1 + 1], ph0, ph1, ph2, ph3, vB[2], vB[3]);
                MMA16816(o[2 * dn0 + 0], ph0, ph1, ph2, ph3, wA[0], wA[1]);
                MMA16816(o[2 * dn0 + 1], ph0, ph1, ph2, ph3, wA[2], wA[3]);
                MMA16816(o[2 * dn1 + 0], ph0, ph1, ph2, ph3, wB[0], wB[1]);
                MMA16816(o[2 * dn1 + 1], ph0, ph1, ph2, ph3, wB[2], wB[3]);
                MMA16816(o[2 * dn0 + 0], pl0, pl1, pl2, pl3, vA[0], vA[1]);
                MMA16816(o[2 * dn0 + 1], pl0, pl1, pl2, pl3, vA[2], vA[3]);
                MMA16816(o[2 * dn1 + 0], pl0, pl1, pl2, pl3, vB[0], vB[1]);
                MMA16816(o[2 * dn1 + 1], pl0, pl1, pl2, pl3, vB[2], vB[3]);
            }
        }
    }

    /* epilogue: normalize, split to bf16 h/l, store */
    const float inv0 = 1.f / lsum0;
    const float inv1 = 1.f / lsum1;
#pragma unroll
    for (int dn = 0; dn < 16; dn++) {
        int col = dn * 8 + 2 * (lid & 3);
        float a0 = o[dn][0] * inv0, a1 = o[dn][1] * inv0;
        float b0 = o[dn][2] * inv1, b1 = o[dn][3] * inv1;
        __nv_bfloat16 ha0 = __float2bfloat16(a0), ha1 = __float2bfloat16(a1);
        __nv_bfloat16 hb0 = __float2bfloat16(b0), hb1 = __float2bfloat16(b1);
        uint32_t hA = packbf(a0, a1);
        uint32_t lA = packbf(a0 - __bfloat162float(ha0), a1 - __bfloat162float(ha1));
        uint32_t hB = packbf(b0, b1);
        uint32_t lB = packbf(b0 - __bfloat162float(hb0), b1 - __bfloat162float(hb1));
        size_t iA = (size_t)r0g * (NH * D) + h * D + col;
        size_t iB = (size_t)r1g * (NH * D) + h * D + col;
        *(uint32_t*)(g_oth + iA) = hA;
        *(uint32_t*)(g_otl + iA) = lA;
        *(uint32_t*)(g_oth + iB) = hB;
        *(uint32_t*)(g_otl + iB) = lB;
    }
}

/* ---------------- launch -------------------------------------------- */
extern "C" void kernel_launch(void* const* d_in, const int* in_sizes, int n_in,
                              void* d_out, int out_size)
{
    const int*   positions = (const int*)d_in[0];
    const float* hidden    = (const float*)d_in[1];
    const float* w_qkv     = (const float*)d_in[2];
    const float* q_norm_w  = (const float*)d_in[3];
    const float* k_norm_w  = (const float*)d_in[4];
    const float* w_o       = (const float*)d_in[5];
    float*       out       = (float*)d_out;
    const int    T         = in_sizes[0];   /* 2048 */

    __nv_bfloat16 *ah, *al, *wqh, *wql, *oh, *ol, *woh, *wol;
    cudaGetSymbolAddress((void**)&ah,  g_ah);
    cudaGetSymbolAddress((void**)&al,  g_al);
    cudaGetSymbolAddress((void**)&wqh, g_wqt_h);
    cudaGetSymbolAddress((void**)&wql, g_wqt_l);
    cudaGetSymbolAddress((void**)&oh,  g_oth);
    cudaGetSymbolAddress((void**)&ol,  g_otl);
    cudaGetSymbolAddress((void**)&woh, g_wot_h);
    cudaGetSymbolAddress((void**)&wol, g_wot_l);

    cudaFuncSetAttribute(tc_gemm, cudaFuncAttributeMaxDynamicSharedMemorySize, GSM_TOTAL);
    cudaFuncSetAttribute(attn_kernel, cudaFuncAttributeMaxDynamicSharedMemorySize, ASM_TOTAL);

    /* 0) inv_freq table + input splits */
    init_freq<<<1, D / 2>>>();
    cvt_split<<<(T * HID) / 1024, 256>>>(hidden, ah, al, T * HID);
    cvt_split_t<<<dim3(QKV_N / 32, HID / 32), dim3(32, 8)>>>(w_qkv, wqh, wql, HID, QKV_N);

    /* 1) QKV projection */
    {
        float* cq;
        cudaGetSymbolAddress((void**)&cq, g_qkv);
        dim3 g(QKV_N / 128, T / 128);
        tc_gemm<<<g, 256, GSM_TOTAL>>>(ah, al, wqh, wql, cq, T, QKV_N, HID);
    }

    /* 2) RMSNorm + RoPE + bf16 splits for q/k/v */
    dim3 g2(T, NH + 2 * NKV);
    normrope_kernel<<<g2, 128>>>(positions, q_norm_w, k_norm_w, T);

    /* 3) causal GQA flash attention */
    dim3 g3(T / 64, NH);
    attn_kernel<<<g3, 128, ASM_TOTAL>>>(T);

    /* 4) output projection */
    cvt_split_t<<<dim3(HID / 32, (NH * D) / 32), dim3(32, 8)>>>(w_o, woh, wol, NH * D, HID);
    {
        dim3 g(HID / 128, T / 128);
        tc_gemm<<<g, 256, GSM_TOTAL>>>(oh, ol, woh, wol, out, T, HID, HID);
    }
}